// round 3
// baseline (speedup 1.0000x reference)
#include <cuda_runtime.h>
#include <cuda_bf16.h>
#include <math.h>

// Problem constants
#define NB    32
#define NPG   256
#define NNODE 8192      // NB*NPG
#define NFEAT 128
#define NHID  64
#define NCLASS 6
#define MIN_NORM 1e-15f
#define MAXN 0.996f     // (1 - PROJ_EPS)/sqrt(c)

// ---------------- scratch (device globals; no allocations allowed) ----------
__device__ float g_sx[NNODE];
__device__ float g_adj1[NB * NPG * NPG];     // 8 MB
__device__ float g_adj2[NB * 128 * 128];     // 2 MB
__device__ float g_adj3[NB * 64 * 64];       // 0.5 MB
__device__ float g_v [NNODE * NHID];
__device__ float g_tA[NNODE * NHID];
__device__ float g_tB[(NNODE/2) * NHID];
__device__ float g_hb[3 * NHID];
__device__ float g_hbn2[3];
__device__ float g_score[NNODE];
__device__ float g_dis[NNODE];
__device__ int   g_sel [NB * 128];
__device__ float g_vals[NB * 128];
__device__ float g_a1[NB * 128];
__device__ float g_a2[NB * 128];
__device__ float g_x1[NB * 2 * NHID];
__device__ float g_x2[NB * 2 * NHID];
__device__ float g_x3[NB * 2 * NHID];

// ---------------- helpers ----------------
__device__ __forceinline__ float artanh_f(float x) {
    x = fminf(fmaxf(x, -1.0f + 1e-7f), 1.0f - 1e-7f);
    return 0.5f * (log1pf(x) - log1pf(-x));
}

// reduction over NW warps (blockDim = 32*NW), shuffle + one smem combine
template<int NW>
__device__ __forceinline__ float bredN(float v, float* buf) {
    int tid = threadIdx.x;
    #pragma unroll
    for (int o = 16; o > 0; o >>= 1) v += __shfl_xor_sync(0xffffffffu, v, o);
    if (NW == 1) return v;
    if ((tid & 31) == 0) buf[tid >> 5] = v;
    __syncthreads();
    float r = 0.0f;
    #pragma unroll
    for (int w = 0; w < NW; w++) r += buf[w];
    __syncthreads();
    return r;
}

// reduction over a 64-thread group inside a 256-thread block (group = tid>>6)
__device__ __forceinline__ float red64g(float v, float* red) {
    int tid = threadIdx.x;
    #pragma unroll
    for (int o = 16; o > 0; o >>= 1) v += __shfl_xor_sync(0xffffffffu, v, o);
    if ((tid & 31) == 0) red[tid >> 5] = v;
    __syncthreads();
    int ns = tid >> 6;
    float r = red[2 * ns] + red[2 * ns + 1];
    __syncthreads();
    return r;
}

// ---------------- stage kernels ----------------

// per-node feature sums for edge weights (128 threads = 4 warps)
__global__ void sx_kernel(const float* __restrict__ x, float* __restrict__ sx) {
    __shared__ float buf[4];
    int i = blockIdx.x;
    float v = x[(size_t)i * NFEAT + threadIdx.x];
    float s = bredN<4>(v, buf);
    if (threadIdx.x == 0) sx[i] = s;
}

__global__ void zero_kernel(float4* __restrict__ p, int n4) {
    int i = blockIdx.x * blockDim.x + threadIdx.x;
    if (i < n4) p[i] = make_float4(0.f, 0.f, 0.f, 0.f);
}

// adj1[g][r%][c%] = 0.5*(sx[r]+sx[c]); duplicates write identical values -> no atomics
__global__ void scatter_kernel(const int* __restrict__ ei, int E,
                               const float* __restrict__ sx, float* __restrict__ adj1) {
    int e = blockIdx.x * blockDim.x + threadIdx.x;
    if (e >= E) return;
    int r = ei[e], c = ei[E + e];
    int g = r >> 8;  // NPG=256
    adj1[(((size_t)g * NPG) + (r & 255)) * NPG + (c & 255)] = 0.5f * (sx[r] + sx[c]);
}

// hb_l = proj(expmap0(b_l)); also its squared norm
__global__ void hb_kernel(const float* __restrict__ b1, const float* __restrict__ b2,
                          const float* __restrict__ b3, float* __restrict__ hb,
                          float* __restrict__ hbn2) {
    __shared__ float buf[2];
    int l = blockIdx.x, tid = threadIdx.x;
    const float* b = (l == 0) ? b1 : (l == 1) ? b2 : b3;
    float u = b[tid];
    float un = fmaxf(sqrtf(bredN<2>(u * u, buf)), MIN_NORM);
    float tu = tanhf(un);
    float s0 = tu / un;
    if (tu > MAXN) s0 *= MAXN / tu;
    float p = u * s0;
    float p2 = bredN<2>(p * p, buf);
    hb[l * NHID + tid] = p;
    if (tid == 0) hbn2[l] = p2;
}

// v = logmap0(proj(mobius_add(proj(mobius_matvec(W, to_hyp(in))), hb)))
// one block (INDIM threads) per node; analytic norms after expmap0/proj
template<int INDIM, int NW>
__global__ void pre_agg_kernel(const float* __restrict__ in,
                               const float* __restrict__ W,
                               const float* __restrict__ hb,
                               const float* __restrict__ hbn2,
                               float* __restrict__ vout) {
    __shared__ float s_x[INDIM];
    __shared__ float buf[NW];
    int node = blockIdx.x, tid = threadIdx.x;

    float u = in[(size_t)node * INDIM + tid];
    // to_hyp = proj(expmap0(u)); norm analytic
    float un = fmaxf(sqrtf(bredN<NW>(u * u, buf)), MIN_NORM);
    float tun = tanhf(un);
    float s0 = tun / un;
    float xn = tun;
    if (tun > MAXN) { s0 *= MAXN / tun; xn = MAXN; }
    s_x[tid] = u * s0;
    __syncthreads();
    // mobius_matvec
    float mx = 0.0f;
    if (tid < NHID) {
        const float* Wr = W + (size_t)tid * INDIM;
        #pragma unroll 8
        for (int k = 0; k < INDIM; k++) mx += Wr[k] * s_x[k];
    }
    float mxn = fmaxf(sqrtf(bredN<NW>((tid < NHID) ? mx * mx : 0.0f, buf)), MIN_NORM);
    float q = mxn / xn * artanh_f(xn);          // >= 0
    float tq = tanhf(q);
    float s1 = tq / mxn;
    float hn = tq;
    if (tq > MAXN) { s1 *= MAXN / tq; hn = MAXN; }
    float hv  = (tid < NHID) ? mx * s1 : 0.0f;
    float hbv = (tid < NHID) ? hb[tid] : 0.0f;
    // mobius_add: x2 analytic, y2 precomputed, xy reduced
    float xy = bredN<NW>(hv * hbv, buf);
    float x2 = hn * hn, y2 = *hbn2;
    float num = (1.0f + 2.0f * xy + y2) * hv + (1.0f - x2) * hbv;
    float den = fmaxf(1.0f + 2.0f * xy + x2 * y2, MIN_NORM);
    float m = num / den;
    // proj + logmap0
    float mn = fmaxf(sqrtf(bredN<NW>((tid < NHID) ? m * m : 0.0f, buf)), MIN_NORM);
    float s2 = 1.0f, pn = mn;
    if (mn > MAXN) { s2 = MAXN / mn; pn = MAXN; }
    if (tid < NHID)
        vout[(size_t)node * NHID + tid] = artanh_f(pn) / pn * (m * s2);
}

// Tiled adj@v + nonlinear chain -> t.
// grid = nb * (npg/32), block 256. Each block: 32 output rows x 64 dims.
__global__ void agg_kernel(const float* __restrict__ adj, int npg,
                           const float* __restrict__ v, float* __restrict__ t) {
    __shared__ float v_s[64][64];      // 16 KB  k-chunk of v
    __shared__ float a_s[32][64];      // 8 KB   adj tile
    __shared__ float y_s[32][65];      // staging for reductions
    __shared__ float red[8];

    int cpg = npg >> 5;                // chunks per graph
    int g  = blockIdx.x / cpg;
    int r0 = (blockIdx.x % cpg) << 5;
    const float* A = adj + ((size_t)g * npg + r0) * npg;
    const float* V = v + (size_t)g * npg * NHID;

    int tid = threadIdx.x;
    int d  = tid & 63;
    int ns = tid >> 6;
    float acc[8];
    #pragma unroll
    for (int i = 0; i < 8; i++) acc[i] = 0.0f;

    for (int k0 = 0; k0 < npg; k0 += 64) {
        #pragma unroll
        for (int i = 0; i < 16; i++) {
            int idx = tid + i * 256;
            ((float*)v_s)[idx] = V[(size_t)k0 * NHID + idx];
        }
        #pragma unroll
        for (int i = 0; i < 8; i++) {
            int idx = tid + i * 256;
            a_s[idx >> 6][idx & 63] = A[(size_t)(idx >> 6) * npg + k0 + (idx & 63)];
        }
        __syncthreads();
        #pragma unroll 8
        for (int k = 0; k < 64; k++) {
            float vv = v_s[k][d];
            #pragma unroll
            for (int n = 0; n < 8; n++)
                acc[n] += a_s[(ns << 3) + n][k] * vv;
        }
        __syncthreads();
    }
    #pragma unroll
    for (int n = 0; n < 8; n++) y_s[(ns << 3) + n][d] = acc[n];
    __syncthreads();

    // nonlinear chain; norms after expmap0 are analytic (tanh of arg norm)
    #pragma unroll 1
    for (int n = 0; n < 8; n++) {
        int node = (ns << 3) + n;
        float y = y_s[node][d];
        float an = fmaxf(sqrtf(red64g(y * y, red)), MIN_NORM);
        float ta = tanhf(an);
        float s1 = ta / an;
        float hn = ta;
        if (ta > MAXN) { s1 *= MAXN / ta; hn = MAXN; }
        float lv = artanh_f(hn) / hn * (y * s1);
        float r = fmaxf(lv, 0.0f);
        float rn = fmaxf(sqrtf(red64g(r * r, red)), MIN_NORM);
        float tr = tanhf(rn);
        float s2 = tr / rn;
        float en = tr;
        if (tr > MAXN) { s2 *= MAXN / tr; en = MAXN; }
        float tval = artanh_f(en) / en * (r * s2);
        t[((size_t)g * npg + r0 + node) * NHID + d] = tval;
    }
}

// warp-per-row degree: dis[i] = deg>0 ? deg^-1/2 : 0
__global__ void deg_kernel(const float* __restrict__ adj, int npg,
                           float* __restrict__ dis, int n) {
    int gw = (blockIdx.x * blockDim.x + threadIdx.x) >> 5;
    int lane = threadIdx.x & 31;
    if (gw >= n) return;
    int g = gw / npg, li = gw % npg;
    const float* arow = adj + ((size_t)g * npg + li) * npg;
    float s = 0.0f;
    for (int k = lane; k < npg; k += 32) s += arow[k];
    #pragma unroll
    for (int o = 16; o > 0; o >>= 1) s += __shfl_xor_sync(0xffffffffu, s, o);
    if (lane == 0) dis[gw] = (s > 0.0f) ? (1.0f / sqrtf(s)) : 0.0f;
}

// Tiled score: score[i] = sum_d | t[i][d] - dis[i]*sum_k adj[i][k]*dis[k]*t[k][d] |
__global__ void score_kernel(const float* __restrict__ adj, int npg,
                             const float* __restrict__ t, const float* __restrict__ dis,
                             float* __restrict__ score) {
    __shared__ float v_s[64][64];
    __shared__ float a_s[32][64];
    __shared__ float red[8];

    int cpg = npg >> 5;
    int g  = blockIdx.x / cpg;
    int r0 = (blockIdx.x % cpg) << 5;
    const float* A = adj + ((size_t)g * npg + r0) * npg;
    const float* T = t + (size_t)g * npg * NHID;
    const float* D = dis + g * npg;

    int tid = threadIdx.x;
    int d  = tid & 63;
    int ns = tid >> 6;
    float acc[8];
    #pragma unroll
    for (int i = 0; i < 8; i++) acc[i] = 0.0f;

    for (int k0 = 0; k0 < npg; k0 += 64) {
        #pragma unroll
        for (int i = 0; i < 16; i++) {
            int idx = tid + i * 256;
            ((float*)v_s)[idx] = T[(size_t)k0 * NHID + idx];
        }
        #pragma unroll
        for (int i = 0; i < 8; i++) {
            int idx = tid + i * 256;
            int kk = idx & 63;
            a_s[idx >> 6][kk] = A[(size_t)(idx >> 6) * npg + k0 + kk] * D[k0 + kk];
        }
        __syncthreads();
        #pragma unroll 8
        for (int k = 0; k < 64; k++) {
            float vv = v_s[k][d];
            #pragma unroll
            for (int n = 0; n < 8; n++)
                acc[n] += a_s[(ns << 3) + n][k] * vv;
        }
        __syncthreads();
    }
    #pragma unroll 1
    for (int n = 0; n < 8; n++) {
        int node = (ns << 3) + n;
        float prop = D[r0 + node] * acc[n];
        float tv = T[(size_t)(r0 + node) * NHID + d];
        float s = red64g(fabsf(tv - prop), red);
        if (d == 0) score[g * npg + r0 + node] = s;
    }
}

// per-graph bitonic sort, descending score, ties -> lower index first
__global__ void topk_kernel(const float* __restrict__ score, int npg, int k,
                            int* __restrict__ sel, float* __restrict__ vals) {
    __shared__ float s[256];
    __shared__ int   id[256];
    int g = blockIdx.x, tid = threadIdx.x;
    s[tid] = score[g * npg + tid];
    id[tid] = tid;
    __syncthreads();
    for (int ksz = 2; ksz <= npg; ksz <<= 1) {
        for (int j = ksz >> 1; j > 0; j >>= 1) {
            int i = tid, ixj = i ^ j;
            if (ixj > i) {
                bool asc = ((i & ksz) == 0);
                float si = s[i], sj = s[ixj];
                int ii = id[i], ij = id[ixj];
                bool i_after_j = (si < sj) || (si == sj && ii > ij);
                if (i_after_j == asc) { s[i] = sj; s[ixj] = si; id[i] = ij; id[ixj] = ii; }
            }
            __syncthreads();
        }
    }
    if (tid < k) { sel[g * k + tid] = id[tid]; vals[g * k + tid] = s[tid]; }
}

// xn = t_old[sel] * tanh(val); a1 = xn.att[:64]; a2 = xn.att[64:]
__global__ void pool_feat_kernel(const float* __restrict__ t_old, int npg, int k,
                                 const int* __restrict__ sel, const float* __restrict__ vals,
                                 const float* __restrict__ att,
                                 float* __restrict__ t_new,
                                 float* __restrict__ a1, float* __restrict__ a2) {
    __shared__ float buf[2];
    int g = blockIdx.x / k, i = blockIdx.x % k, tid = threadIdx.x;
    int li = sel[g * k + i];
    float tn = tanhf(vals[g * k + i]);
    float xv = t_old[((size_t)g * npg + li) * NHID + tid] * tn;
    t_new[((size_t)g * k + i) * NHID + tid] = xv;
    float r1 = bredN<2>(xv * att[tid], buf);
    float r2 = bredN<2>(xv * att[NHID + tid], buf);
    if (tid == 0) { a1[g * k + i] = r1; a2[g * k + i] = r2; }
}

// new_adj[i][j] = max(a1_i + a2_j, 0) + adj_old[sel_i][sel_j]   (within graph)
__global__ void new_adj_kernel(const float* __restrict__ adj_old, int npg, int k,
                               const int* __restrict__ sel,
                               const float* __restrict__ a1, const float* __restrict__ a2,
                               float* __restrict__ adj_new) {
    int g = blockIdx.x / k, i = blockIdx.x % k, j = threadIdx.x;
    int si = sel[g * k + i], sj = sel[g * k + j];
    float e = a1[g * k + i] + a2[g * k + j];
    float val = fmaxf(e, 0.0f) + adj_old[((size_t)g * npg + si) * npg + sj];
    adj_new[((size_t)g * k + i) * k + j] = val;
}

// per-graph concat(max over nodes, mean over nodes)
__global__ void readout_kernel(const float* __restrict__ t, int k, float* __restrict__ out) {
    int g = blockIdx.x, d = threadIdx.x;  // 64 threads
    float mx = -INFINITY, sm = 0.0f;
    for (int i = 0; i < k; i++) {
        float v = t[((size_t)g * k + i) * NHID + d];
        mx = fmaxf(mx, v);
        sm += v;
    }
    out[g * 2 * NHID + d] = mx;
    out[g * 2 * NHID + NHID + d] = sm / (float)k;
}

__global__ void mlp_kernel(const float* __restrict__ x1, const float* __restrict__ x2,
                           const float* __restrict__ x3,
                           const float* __restrict__ lw1, const float* __restrict__ lb1,
                           const float* __restrict__ lw2, const float* __restrict__ lb2,
                           const float* __restrict__ lw3, const float* __restrict__ lb3,
                           float* __restrict__ out) {
    __shared__ float r0[2 * NHID];
    __shared__ float r1[NHID];
    __shared__ float r2[NHID / 2];
    int g = blockIdx.x, tid = threadIdx.x;  // 128 threads
    {
        float a = fmaxf(x1[g * 128 + tid], 0.0f) + fmaxf(x2[g * 128 + tid], 0.0f)
                + fmaxf(x3[g * 128 + tid], 0.0f);
        r0[tid] = a;
    }
    __syncthreads();
    if (tid < NHID) {
        float acc = lb1[tid];
        #pragma unroll 8
        for (int k = 0; k < 128; k++) acc += lw1[tid * 128 + k] * r0[k];
        r1[tid] = fmaxf(acc, 0.0f);
    }
    __syncthreads();
    if (tid < 32) {
        float acc = lb2[tid];
        #pragma unroll 8
        for (int k = 0; k < 64; k++) acc += lw2[tid * 64 + k] * r1[k];
        r2[tid] = fmaxf(acc, 0.0f);
    }
    __syncthreads();
    if (tid == 0) {
        float l[NCLASS];
        float m = -INFINITY;
        for (int j = 0; j < NCLASS; j++) {
            float acc = lb3[j];
            for (int k = 0; k < 32; k++) acc += lw3[j * 32 + k] * r2[k];
            l[j] = acc;
            m = fmaxf(m, acc);
        }
        float s = 0.0f;
        for (int j = 0; j < NCLASS; j++) s += expf(l[j] - m);
        float lse = m + logf(s);
        for (int j = 0; j < NCLASS; j++) out[g * NCLASS + j] = l[j] - lse;
    }
}

// ---------------- launch ----------------
extern "C" void kernel_launch(void* const* d_in, const int* in_sizes, int n_in,
                              void* d_out, int out_size) {
    const float* x    = (const float*)d_in[0];
    const int*   ei   = (const int*)d_in[1];
    const float* W1   = (const float*)d_in[2];
    const float* b1   = (const float*)d_in[3];
    const float* W2   = (const float*)d_in[4];
    const float* b2   = (const float*)d_in[5];
    const float* W3   = (const float*)d_in[6];
    const float* b3   = (const float*)d_in[7];
    const float* att1 = (const float*)d_in[8];
    const float* att2 = (const float*)d_in[9];
    const float* lw1  = (const float*)d_in[10];
    const float* lb1  = (const float*)d_in[11];
    const float* lw2  = (const float*)d_in[12];
    const float* lb2  = (const float*)d_in[13];
    const float* lw3  = (const float*)d_in[14];
    const float* lb3  = (const float*)d_in[15];

    int E = in_sizes[1] / 2;

    float *sx, *adj1, *adj2, *adj3, *v, *tA, *tB, *hb, *hbn2, *score, *dis, *vals, *a1, *a2, *x1b, *x2b, *x3b;
    int* sel;
    cudaGetSymbolAddress((void**)&sx,   g_sx);
    cudaGetSymbolAddress((void**)&adj1, g_adj1);
    cudaGetSymbolAddress((void**)&adj2, g_adj2);
    cudaGetSymbolAddress((void**)&adj3, g_adj3);
    cudaGetSymbolAddress((void**)&v,    g_v);
    cudaGetSymbolAddress((void**)&tA,   g_tA);
    cudaGetSymbolAddress((void**)&tB,   g_tB);
    cudaGetSymbolAddress((void**)&hb,   g_hb);
    cudaGetSymbolAddress((void**)&hbn2, g_hbn2);
    cudaGetSymbolAddress((void**)&score,g_score);
    cudaGetSymbolAddress((void**)&dis,  g_dis);
    cudaGetSymbolAddress((void**)&sel,  g_sel);
    cudaGetSymbolAddress((void**)&vals, g_vals);
    cudaGetSymbolAddress((void**)&a1,   g_a1);
    cudaGetSymbolAddress((void**)&a2,   g_a2);
    cudaGetSymbolAddress((void**)&x1b,  g_x1);
    cudaGetSymbolAddress((void**)&x2b,  g_x2);
    cudaGetSymbolAddress((void**)&x3b,  g_x3);

    // ---- build adj1 ----
    sx_kernel<<<NNODE, NFEAT>>>(x, sx);
    zero_kernel<<<(NB * NPG * NPG / 4 + 255) / 256, 256>>>((float4*)adj1, NB * NPG * NPG / 4);
    scatter_kernel<<<(E + 255) / 256, 256>>>(ei, E, sx, adj1);
    hb_kernel<<<3, NHID>>>(b1, b2, b3, hb, hbn2);

    // ---- layer 1 (8192 nodes, in_dim 128) ----
    pre_agg_kernel<NFEAT, 4><<<NNODE, NFEAT>>>(x, W1, hb, hbn2, v);
    agg_kernel<<<NB * (NPG / 32), 256>>>(adj1, NPG, v, tA);
    deg_kernel<<<(NNODE * 32 + 255) / 256, 256>>>(adj1, NPG, dis, NNODE);
    score_kernel<<<NB * (NPG / 32), 256>>>(adj1, NPG, tA, dis, score);
    topk_kernel<<<NB, NPG>>>(score, NPG, 128, sel, vals);
    pool_feat_kernel<<<NB * 128, NHID>>>(tA, NPG, 128, sel, vals, att1, tB, a1, a2);
    new_adj_kernel<<<NB * 128, 128>>>(adj1, NPG, 128, sel, a1, a2, adj2);
    readout_kernel<<<NB, NHID>>>(tB, 128, x1b);

    // ---- layer 2 (4096 nodes, in_dim 64) ----
    pre_agg_kernel<NHID, 2><<<NB * 128, NHID>>>(tB, W2, hb + NHID, hbn2 + 1, v);
    agg_kernel<<<NB * (128 / 32), 256>>>(adj2, 128, v, tA);
    deg_kernel<<<(NB * 128 * 32 + 255) / 256, 256>>>(adj2, 128, dis, NB * 128);
    score_kernel<<<NB * (128 / 32), 256>>>(adj2, 128, tA, dis, score);
    topk_kernel<<<NB, 128>>>(score, 128, 64, sel, vals);
    pool_feat_kernel<<<NB * 64, NHID>>>(tA, 128, 64, sel, vals, att2, tB, a1, a2);
    new_adj_kernel<<<NB * 64, 64>>>(adj2, 128, 64, sel, a1, a2, adj3);
    readout_kernel<<<NB, NHID>>>(tB, 64, x2b);

    // ---- layer 3 (2048 nodes, in_dim 64) ----
    pre_agg_kernel<NHID, 2><<<NB * 64, NHID>>>(tB, W3, hb + 2 * NHID, hbn2 + 2, v);
    agg_kernel<<<NB * (64 / 32), 256>>>(adj3, 64, v, tA);
    readout_kernel<<<NB, NHID>>>(tA, 64, x3b);

    // ---- MLP head ----
    mlp_kernel<<<NB, 128>>>(x1b, x2b, x3b, lw1, lb1, lw2, lb2, lw3, lb3, (float*)d_out);
}

// round 4
// speedup vs baseline: 5.2831x; 5.2831x over previous
#include <cuda_runtime.h>
#include <cuda_bf16.h>
#include <math.h>

#define NB    32
#define NPG   256
#define GS    256          // per-graph row stride for all node buffers
#define NHID  64
#define NCLASS 6
#define MIN_NORM 1e-15f
#define MAXN 0.996f

#define NTHREADS 512
#define GRID     (NB * 4)

// ---------------- global scratch ----------------
__device__ float g_sx[NB * NPG];
__device__ float g_adj1[NB * 256 * 256];
__device__ float g_adj2[NB * 128 * 128];
__device__ float g_adj3[NB * 64 * 64];
__device__ float g_v  [NB * GS * 64];
__device__ float g_tA [NB * GS * 64];
__device__ float g_tB [NB * GS * 64];
__device__ float g_dis[NB * GS];
__device__ float g_score[NB * GS];
__device__ float g_a1[NB * 128];
__device__ float g_a2[NB * 128];

// ---------------- smem layout (floats) ----------------
// persist:
#define SM_HB     0        // 192
#define SM_HBN2   192      // 4
#define SM_RED    196      // 16
#define SM_SORTS  212      // 256
#define SM_SORTID 468      // 256 (int)
#define SM_SELS   724      // 128 (int)
#define SM_VALS   852      // 128
#define SM_X1R    980      // 128
#define SM_X2R    1108     // 128
#define SM_X3R    1236     // 128
#define SM_XN     1364     // 64
#define SM_MLP0   1428     // 128
#define SM_MLP1   1556     // 64
#define SM_MLP2   1620     // 32
#define SM_SCR    1664
// SCR union:
//   pre_agg: Wt[128*68]=8704 | xh[64*130]=8320 | mx[64*68]=4352  (21376)
//   agg:     v_s[256*64]=16384 | a_s[32*257]=8224                (24608)
#define SCR_WT_OFF   0
#define SCR_XH_OFF   8704
#define SCR_MX_OFF   (8704 + 8320)
#define SCR_VS_OFF   0
#define SCR_AS_OFF   16384
#define SM_TOTALF    (1664 + 24608)
#define SMEM_BYTES   (SM_TOTALF * 4)

#define CSYNC() do { asm volatile("barrier.cluster.arrive.aligned;" ::: "memory"); \
                     asm volatile("barrier.cluster.wait.aligned;"   ::: "memory"); } while (0)

// ---------------- helpers ----------------
__device__ __forceinline__ float artanh_f(float x) {
    x = fminf(fmaxf(x, -1.0f + 1e-7f), 1.0f - 1e-7f);
    return 0.5f * (log1pf(x) - log1pf(-x));
}

// reduce over groups of 64 threads (group = tid>>6); all 512 threads must call
__device__ __forceinline__ float red64(float v, float* red) {
    int tid = threadIdx.x;
    #pragma unroll
    for (int o = 16; o > 0; o >>= 1) v += __shfl_xor_sync(0xffffffffu, v, o);
    if ((tid & 31) == 0) red[tid >> 5] = v;
    __syncthreads();
    float r = red[(tid >> 6) * 2] + red[(tid >> 6) * 2 + 1];
    __syncthreads();
    return r;
}

// reduce over groups of 16 lanes (aligned half-half-warps)
__device__ __forceinline__ float hwred16(float v) {
    v += __shfl_xor_sync(0xffffffffu, v, 8);
    v += __shfl_xor_sync(0xffffffffu, v, 4);
    v += __shfl_xor_sync(0xffffffffu, v, 2);
    v += __shfl_xor_sync(0xffffffffu, v, 1);
    return v;
}

// ---------------- phase functions ----------------

// v = logmap0(proj(mobius_add(proj(mobius_matvec(W, to_hyp(in))), hb)))
template<int IN>
__device__ void pre_agg(const float* __restrict__ in, int nodes_q,
                        const float* __restrict__ W,
                        const float* hb, float hbn2v,
                        float* __restrict__ vout, float* SCR, float* RED, float* XN) {
    int tid = threadIdx.x;
    float* Wt = SCR + SCR_WT_OFF;   // [IN][68]
    float* xh = SCR + SCR_XH_OFF;   // [nodes_q][IN+2]
    float* mx = SCR + SCR_MX_OFF;   // [nodes_q][68]
    const int XHP = IN + 2;

    for (int idx = tid; idx < 64 * IN; idx += NTHREADS) {
        int o = idx / IN, k = idx - o * IN;
        Wt[k * 68 + o] = W[idx];
    }
    if (tid < nodes_q * 8) {
        int node = tid >> 3, j = tid & 7;
        const int per = IN >> 3;                     // 16 or 8
        const float* ur = in + (size_t)node * IN + j * per;
        float u[per];
        float s = 0.f;
        #pragma unroll
        for (int t = 0; t < per; t++) { u[t] = ur[t]; s += u[t] * u[t]; }
        s += __shfl_xor_sync(0xffffffffu, s, 4);
        s += __shfl_xor_sync(0xffffffffu, s, 2);
        s += __shfl_xor_sync(0xffffffffu, s, 1);
        float un = fmaxf(sqrtf(s), MIN_NORM);
        float tu = tanhf(un);
        float s0 = tu / un, xn = tu;
        if (tu > MAXN) { s0 *= MAXN / tu; xn = MAXN; }
        float* xrow = xh + node * XHP + j * per;
        #pragma unroll
        for (int t = 0; t < per; t++) xrow[t] = u[t] * s0;
        if (j == 0) XN[node] = xn;
    }
    __syncthreads();
    // GEMM: mx[n][o] = sum_k xh[n][k] * W[o][k]
    int passes = (nodes_q + 31) >> 5;
    for (int p = 0; p < passes; p++) {
        int myrow = p * 32 + (tid >> 4);
        int o4 = (tid & 15) << 2;
        if (myrow < nodes_q) {
            const float* xr = xh + myrow * XHP;
            float4 acc = make_float4(0.f, 0.f, 0.f, 0.f);
            #pragma unroll 8
            for (int k = 0; k < IN; k++) {
                float xv = xr[k];
                float4 w4 = *(const float4*)(Wt + k * 68 + o4);
                acc.x += xv * w4.x; acc.y += xv * w4.y;
                acc.z += xv * w4.z; acc.w += xv * w4.w;
            }
            *(float4*)(mx + myrow * 68 + o4) = acc;
        }
    }
    __syncthreads();
    // per-node nonlinear (groups of 64)
    int outers = nodes_q >> 3;
    for (int ou = 0; ou < outers; ou++) {
        int node = ou * 8 + (tid >> 6);
        int d = tid & 63;
        float mxv = mx[node * 68 + d];
        float mxn = fmaxf(sqrtf(red64(mxv * mxv, RED)), MIN_NORM);
        float xnv = XN[node];
        float qv = mxn / xnv * artanh_f(xnv);
        float tq = tanhf(qv);
        float s1 = tq / mxn, hn = tq;
        if (tq > MAXN) { s1 *= MAXN / tq; hn = MAXN; }
        float hv = mxv * s1;
        float hbv = hb[d];
        float xy = red64(hv * hbv, RED);
        float x2 = hn * hn, y2 = hbn2v;
        float num = (1.f + 2.f * xy + y2) * hv + (1.f - x2) * hbv;
        float den = fmaxf(1.f + 2.f * xy + x2 * y2, MIN_NORM);
        float m = num / den;
        float mn = fmaxf(sqrtf(red64(m * m, RED)), MIN_NORM);
        float s2 = 1.f, pn = mn;
        if (mn > MAXN) { s2 = MAXN / mn; pn = MAXN; }
        vout[(size_t)node * 64 + d] = artanh_f(pn) / pn * (m * s2);
    }
}

// t = logmap0(proj(expmap0(relu(logmap0(proj(expmap0(adj@v))))))); also deg
__device__ void agg_deg(const float* __restrict__ adjg, int npg, int q,
                        const float* __restrict__ vg, float* __restrict__ tg,
                        float* __restrict__ disg, float* SCR) {
    int tid = threadIdx.x;
    float* v_s = SCR + SCR_VS_OFF;
    float* a_s = SCR + SCR_AS_OFF;
    const int AP = npg + 1;
    for (int idx = tid; idx < npg * 64; idx += NTHREADS) v_s[idx] = vg[idx];
    __syncthreads();
    int R = npg >> 2;
    int rowbase0 = q * R;
    int passes = (R + 31) >> 5;
    for (int p = 0; p < passes; p++) {
        int rowb = rowbase0 + p * 32;
        int nrows = min(32, R - p * 32);
        for (int idx = tid; idx < nrows * npg; idx += NTHREADS) {
            int r = idx / npg, k = idx - r * npg;
            a_s[r * AP + k] = adjg[(size_t)(rowb + r) * npg + k];
        }
        __syncthreads();
        int rs = tid >> 4, d4 = (tid & 15) << 2;
        bool act = rs < nrows;
        float4 acc = make_float4(0.f, 0.f, 0.f, 0.f);
        float dsum = 0.f;
        if (act) {
            const float* ar = a_s + rs * AP;
            #pragma unroll 4
            for (int k = 0; k < npg; k++) {
                float a = ar[k];
                float4 v4 = *(const float4*)(v_s + k * 64 + d4);
                acc.x += a * v4.x; acc.y += a * v4.y;
                acc.z += a * v4.z; acc.w += a * v4.w;
                dsum += a;
            }
        }
        float an2 = hwred16(acc.x*acc.x + acc.y*acc.y + acc.z*acc.z + acc.w*acc.w);
        float an = fmaxf(sqrtf(an2), MIN_NORM);
        float ta = tanhf(an);
        float s1 = ta / an, hn = ta;
        if (ta > MAXN) { s1 *= MAXN / ta; hn = MAXN; }
        float lf = artanh_f(hn) / hn * s1;
        float4 rr;
        rr.x = fmaxf(acc.x * lf, 0.f); rr.y = fmaxf(acc.y * lf, 0.f);
        rr.z = fmaxf(acc.z * lf, 0.f); rr.w = fmaxf(acc.w * lf, 0.f);
        float rn2 = hwred16(rr.x*rr.x + rr.y*rr.y + rr.z*rr.z + rr.w*rr.w);
        float rn = fmaxf(sqrtf(rn2), MIN_NORM);
        float tr = tanhf(rn);
        float s2 = tr / rn, en = tr;
        if (tr > MAXN) { s2 *= MAXN / tr; en = MAXN; }
        float tf = artanh_f(en) / en * s2;
        if (act) {
            float4 tv = make_float4(rr.x*tf, rr.y*tf, rr.z*tf, rr.w*tf);
            *(float4*)(tg + (size_t)(rowb + rs) * 64 + d4) = tv;
            if ((tid & 15) == 0)
                disg[rowb + rs] = (dsum > 0.f) ? (1.f / sqrtf(dsum)) : 0.f;
        }
        __syncthreads();
    }
}

// score[i] = sum_d | t[i][d] - dis[i]*sum_k adj[i][k]*dis[k]*t[k][d] |
__device__ void score_phase(const float* __restrict__ adjg, int npg, int q,
                            const float* __restrict__ tg, const float* __restrict__ disg,
                            float* __restrict__ scoreg, float* SCR) {
    int tid = threadIdx.x;
    float* v_s = SCR + SCR_VS_OFF;
    float* a_s = SCR + SCR_AS_OFF;
    const int AP = npg + 1;
    for (int idx = tid; idx < npg * 64; idx += NTHREADS) v_s[idx] = tg[idx];
    __syncthreads();
    int R = npg >> 2;
    int rowbase0 = q * R;
    int passes = (R + 31) >> 5;
    for (int p = 0; p < passes; p++) {
        int rowb = rowbase0 + p * 32;
        int nrows = min(32, R - p * 32);
        for (int idx = tid; idx < nrows * npg; idx += NTHREADS) {
            int r = idx / npg, k = idx - r * npg;
            a_s[r * AP + k] = adjg[(size_t)(rowb + r) * npg + k] * disg[k];
        }
        __syncthreads();
        int rs = tid >> 4, d4 = (tid & 15) << 2;
        bool act = rs < nrows;
        float4 acc = make_float4(0.f, 0.f, 0.f, 0.f);
        float disr = 0.f;
        float4 t4 = make_float4(0.f, 0.f, 0.f, 0.f);
        if (act) {
            const float* ar = a_s + rs * AP;
            #pragma unroll 4
            for (int k = 0; k < npg; k++) {
                float a = ar[k];
                float4 v4 = *(const float4*)(v_s + k * 64 + d4);
                acc.x += a * v4.x; acc.y += a * v4.y;
                acc.z += a * v4.z; acc.w += a * v4.w;
            }
            disr = disg[rowb + rs];
            t4 = *(const float4*)(v_s + (size_t)(rowb + rs) * 64 + d4);
        }
        float sc = hwred16(fabsf(t4.x - disr * acc.x) + fabsf(t4.y - disr * acc.y) +
                           fabsf(t4.z - disr * acc.z) + fabsf(t4.w - disr * acc.w));
        if (act && (tid & 15) == 0) scoreg[rowb + rs] = sc;
        __syncthreads();
    }
}

// bitonic sort, descending by score, ties -> smaller index first
__device__ void topk(int n, int kk, const float* __restrict__ scoreg,
                     float* SORTS, int* SORTID, int* SELS, float* VALS) {
    int tid = threadIdx.x;
    if (tid < n) { SORTS[tid] = scoreg[tid]; SORTID[tid] = tid; }
    __syncthreads();
    for (int ksz = 2; ksz <= n; ksz <<= 1)
        for (int j = ksz >> 1; j > 0; j >>= 1) {
            if (tid < n) {
                int ixj = tid ^ j;
                if (ixj > tid) {
                    bool asc = (tid & ksz) == 0;
                    float si = SORTS[tid], sj = SORTS[ixj];
                    int ii = SORTID[tid], ij = SORTID[ixj];
                    bool after = (si < sj) || (si == sj && ii > ij);
                    if (after == asc) {
                        SORTS[tid] = sj; SORTS[ixj] = si;
                        SORTID[tid] = ij; SORTID[ixj] = ii;
                    }
                }
            }
            __syncthreads();
        }
    if (tid < kk) { SELS[tid] = SORTID[tid]; VALS[tid] = SORTS[tid]; }
    __syncthreads();
}

__device__ void pool(int kk, int q, const float* __restrict__ tg,
                     const float* __restrict__ att,
                     float* __restrict__ tBg, float* __restrict__ a1g, float* __restrict__ a2g,
                     const int* SELS, const float* VALS, float* RED) {
    int tid = threadIdx.x;
    int qn = kk >> 2;
    int outers = qn >> 3;
    for (int ou = 0; ou < outers; ou++) {
        int i = q * qn + ou * 8 + (tid >> 6);
        int d = tid & 63;
        int li = SELS[i];
        float tn = tanhf(VALS[i]);
        float xv = tg[(size_t)li * 64 + d] * tn;
        tBg[(size_t)i * 64 + d] = xv;
        float r1 = red64(xv * att[d], RED);
        float r2 = red64(xv * att[64 + d], RED);
        if (d == 0) { a1g[i] = r1; a2g[i] = r2; }
    }
}

__device__ void new_adj(const float* __restrict__ adjsrcg, int npg, int kk, int q,
                        const float* __restrict__ a1g, const float* __restrict__ a2g,
                        const int* SELS, float* __restrict__ adjdstg) {
    int tid = threadIdx.x;
    int qn = kk >> 2;
    int total = qn * kk;
    for (int idx = tid; idx < total; idx += NTHREADS) {
        int il = idx / kk;
        int i = q * qn + il;
        int j = idx - il * kk;
        float e = a1g[i] + a2g[j];
        adjdstg[(size_t)i * kk + j] =
            fmaxf(e, 0.f) + adjsrcg[(size_t)SELS[i] * npg + SELS[j]];
    }
}

__device__ void readout(const float* __restrict__ tg, int kk, float* XR) {
    int tid = threadIdx.x;
    if (tid < 64) {
        float mx = -INFINITY, sm = 0.f;
        for (int i = 0; i < kk; i++) {
            float v = tg[(size_t)i * 64 + tid];
            mx = fmaxf(mx, v); sm += v;
        }
        XR[tid] = mx; XR[64 + tid] = sm / (float)kk;
    }
    __syncthreads();
}

// ---------------- megakernel ----------------
extern __shared__ float sm[];

__global__ void __cluster_dims__(4, 1, 1) __launch_bounds__(NTHREADS, 1)
mega_kernel(const float* __restrict__ x, const int* __restrict__ ei, int E,
            const float* __restrict__ W1, const float* __restrict__ b1,
            const float* __restrict__ W2, const float* __restrict__ b2,
            const float* __restrict__ W3, const float* __restrict__ b3,
            const float* __restrict__ att1, const float* __restrict__ att2,
            const float* __restrict__ lw1, const float* __restrict__ lb1,
            const float* __restrict__ lw2, const float* __restrict__ lb2,
            const float* __restrict__ lw3, const float* __restrict__ lb3,
            float* __restrict__ out) {
    float* HB   = sm + SM_HB;
    float* HBN2 = sm + SM_HBN2;
    float* RED  = sm + SM_RED;
    float* SORTS = sm + SM_SORTS;
    int*   SORTID = (int*)(sm + SM_SORTID);
    int*   SELS = (int*)(sm + SM_SELS);
    float* VALS = sm + SM_VALS;
    float* X1R = sm + SM_X1R;
    float* X2R = sm + SM_X2R;
    float* X3R = sm + SM_X3R;
    float* XN  = sm + SM_XN;
    float* MLP0 = sm + SM_MLP0;
    float* MLP1 = sm + SM_MLP1;
    float* MLP2 = sm + SM_MLP2;
    float* SCR = sm + SM_SCR;

    int g = blockIdx.x >> 2, q = blockIdx.x & 3, tid = threadIdx.x;

    float* adj1g = g_adj1 + (size_t)g * 256 * 256;
    float* adj2g = g_adj2 + (size_t)g * 128 * 128;
    float* adj3g = g_adj3 + (size_t)g * 64 * 64;
    float* vg   = g_v   + (size_t)g * GS * 64;
    float* tAg  = g_tA  + (size_t)g * GS * 64;
    float* tBg  = g_tB  + (size_t)g * GS * 64;
    float* disg = g_dis + (size_t)g * GS;
    float* scoreg = g_score + (size_t)g * GS;
    float* a1g = g_a1 + g * 128;
    float* a2g = g_a2 + g * 128;

    // hb = proj(expmap0(b_l)), all 3 layers, per-block local
    {
        int l = tid >> 6, d = tid & 63;
        float u = (l < 3) ? ((l == 0 ? b1 : (l == 1 ? b2 : b3))[d]) : 0.f;
        float un2 = red64(u * u, RED);
        if (l < 3) {
            float un = fmaxf(sqrtf(un2), MIN_NORM);
            float tu = tanhf(un);
            float s0 = tu / un, pn = tu;
            if (tu > MAXN) { s0 *= MAXN / tu; pn = MAXN; }
            HB[l * 64 + d] = u * s0;
            if (d == 0) HBN2[l] = pn * pn;
        }
    }
    __syncthreads();

    // Phase A: sx (quarter), zero adj1 (quarter rows), pre_agg L1 (quarter)
    {
        int node = tid >> 3, j = tid & 7;
        int gn = g * NPG + q * 64 + node;
        const float4* xr = (const float4*)(x + (size_t)gn * 128 + j * 16);
        float s = 0.f;
        #pragma unroll
        for (int p = 0; p < 4; p++) { float4 v4 = xr[p]; s += v4.x + v4.y + v4.z + v4.w; }
        s += __shfl_xor_sync(0xffffffffu, s, 4);
        s += __shfl_xor_sync(0xffffffffu, s, 2);
        s += __shfl_xor_sync(0xffffffffu, s, 1);
        if (j == 0) g_sx[gn] = s;
    }
    {
        float4* dst = (float4*)(adj1g + (size_t)q * 64 * 256);
        for (int i = tid; i < 64 * 256 / 4; i += NTHREADS) dst[i] = make_float4(0.f, 0.f, 0.f, 0.f);
    }
    pre_agg<128>(x + (size_t)(g * NPG + q * 64) * 128, 64, W1, HB, HBN2[0],
                 vg + (size_t)(q * 64) * 64, SCR, RED, XN);
    CSYNC();

    // Phase B: scatter this quarter's share of the graph's edges
    {
        int Eg = E / NB;
        for (int t = q + 4 * tid; t < Eg; t += 4 * NTHREADS) {
            int e = g * Eg + t;
            int r = ei[e], c = ei[E + e];
            adj1g[(size_t)(r & 255) * 256 + (c & 255)] = 0.5f * (g_sx[r] + g_sx[c]);
        }
    }
    CSYNC();

    agg_deg(adj1g, 256, q, vg, tAg, disg, SCR);
    CSYNC();
    score_phase(adj1g, 256, q, tAg, disg, scoreg, SCR);
    CSYNC();
    topk(256, 128, scoreg, SORTS, SORTID, SELS, VALS);
    pool(128, q, tAg, att1, tBg, a1g, a2g, SELS, VALS, RED);
    CSYNC();
    new_adj(adj1g, 256, 128, q, a1g, a2g, SELS, adj2g);
    pre_agg<64>(tBg + (size_t)(q * 32) * 64, 32, W2, HB + 64, HBN2[1],
                vg + (size_t)(q * 32) * 64, SCR, RED, XN);
    readout(tBg, 128, X1R);
    CSYNC();
    agg_deg(adj2g, 128, q, vg, tAg, disg, SCR);
    CSYNC();
    score_phase(adj2g, 128, q, tAg, disg, scoreg, SCR);
    CSYNC();
    topk(128, 64, scoreg, SORTS, SORTID, SELS, VALS);
    pool(64, q, tAg, att2, tBg, a1g, a2g, SELS, VALS, RED);
    CSYNC();
    new_adj(adj2g, 128, 64, q, a1g, a2g, SELS, adj3g);
    pre_agg<64>(tBg + (size_t)(q * 16) * 64, 16, W3, HB + 128, HBN2[2],
                vg + (size_t)(q * 16) * 64, SCR, RED, XN);
    readout(tBg, 64, X2R);
    CSYNC();
    agg_deg(adj3g, 64, q, vg, tAg, disg, SCR);
    CSYNC();
    readout(tAg, 64, X3R);

    // MLP head (redundant per block; q==0 writes)
    if (tid < 128)
        MLP0[tid] = fmaxf(X1R[tid], 0.f) + fmaxf(X2R[tid], 0.f) + fmaxf(X3R[tid], 0.f);
    __syncthreads();
    if (tid < 64) {
        float acc = lb1[tid];
        #pragma unroll 8
        for (int k = 0; k < 128; k++) acc += lw1[tid * 128 + k] * MLP0[k];
        MLP1[tid] = fmaxf(acc, 0.f);
    }
    __syncthreads();
    if (tid < 32) {
        float acc = lb2[tid];
        #pragma unroll 8
        for (int k = 0; k < 64; k++) acc += lw2[tid * 64 + k] * MLP1[k];
        MLP2[tid] = fmaxf(acc, 0.f);
    }
    __syncthreads();
    if (tid == 0 && q == 0) {
        float l[NCLASS];
        float m = -INFINITY;
        for (int j = 0; j < NCLASS; j++) {
            float acc = lb3[j];
            for (int k = 0; k < 32; k++) acc += lw3[j * 32 + k] * MLP2[k];
            l[j] = acc;
            m = fmaxf(m, acc);
        }
        float s = 0.f;
        for (int j = 0; j < NCLASS; j++) s += expf(l[j] - m);
        float lse = m + logf(s);
        for (int j = 0; j < NCLASS; j++) out[g * NCLASS + j] = l[j] - lse;
    }
}

// ---------------- launch ----------------
extern "C" void kernel_launch(void* const* d_in, const int* in_sizes, int n_in,
                              void* d_out, int out_size) {
    const float* x    = (const float*)d_in[0];
    const int*   ei   = (const int*)d_in[1];
    const float* W1   = (const float*)d_in[2];
    const float* b1   = (const float*)d_in[3];
    const float* W2   = (const float*)d_in[4];
    const float* b2   = (const float*)d_in[5];
    const float* W3   = (const float*)d_in[6];
    const float* b3   = (const float*)d_in[7];
    const float* att1 = (const float*)d_in[8];
    const float* att2 = (const float*)d_in[9];
    const float* lw1  = (const float*)d_in[10];
    const float* lb1  = (const float*)d_in[11];
    const float* lw2  = (const float*)d_in[12];
    const float* lb2  = (const float*)d_in[13];
    const float* lw3  = (const float*)d_in[14];
    const float* lb3  = (const float*)d_in[15];

    int E = in_sizes[1] / 2;

    cudaFuncSetAttribute(mega_kernel, cudaFuncAttributeMaxDynamicSharedMemorySize, SMEM_BYTES);
    mega_kernel<<<GRID, NTHREADS, SMEM_BYTES>>>(
        x, ei, E, W1, b1, W2, b2, W3, b3, att1, att2,
        lw1, lb1, lw2, lb2, lw3, lb3, (float*)d_out);
}

// round 5
// speedup vs baseline: 7.8370x; 1.4834x over previous
#include <cuda_runtime.h>
#include <cuda_bf16.h>
#include <math.h>

#define NB    32
#define NPG   256
#define GS    256
#define NCLASS 6
#define MIN_NORM 1e-15f
#define MAXN 0.996f

#define NTHREADS 512
#define GRID     (NB * 4)

// ---------------- global scratch ----------------
__device__ float g_sx[NB * NPG];
__device__ float g_adj1[NB * 256 * 256];
__device__ float g_adj2[NB * 128 * 128];
__device__ float g_adj3[NB * 64 * 64];
__device__ float g_v  [NB * GS * 64];
__device__ float g_tA [NB * GS * 64];
__device__ float g_tB [NB * GS * 64];
__device__ float g_dis[NB * GS];
__device__ float g_score[NB * GS];

// ---------------- smem layout (floats) ----------------
#define SM_HB     0        // 192
#define SM_HBN2   192      // 4
#define SM_RED    196      // 16
#define SM_SORTS  212      // 256
#define SM_SORTID 468      // 256 (int)
#define SM_SELS   724      // 128 (int)
#define SM_VALS   852      // 128
#define SM_SA1    980      // 128
#define SM_SA2    1108     // 128
#define SM_X1R    1236     // 128
#define SM_X2R    1364     // 128
#define SM_X3R    1492     // 128
#define SM_XN     1620     // 64
#define SM_MLP0   1684     // 128
#define SM_MLP1   1812     // 64
#define SM_MLP2   1876     // 32
#define SM_SCR    1920
// SCR union: agg L1: v_s 256*64=16384 + a_s 64*260=16640 -> 33024
//            pre_agg L1: Wt 128*68=8704 + xh 64*132=8448 -> 17152
#define SM_TOTALF (1920 + 33024)
#define SMEM_BYTES (SM_TOTALF * 4)

#define CSYNC() do { asm volatile("barrier.cluster.arrive.aligned;" ::: "memory"); \
                     asm volatile("barrier.cluster.wait.aligned;"   ::: "memory"); } while (0)

// ---------------- helpers ----------------
__device__ __forceinline__ float artanh_f(float x) {
    x = fminf(fmaxf(x, -1.0f + 1e-7f), 1.0f - 1e-7f);
    return 0.5f * (log1pf(x) - log1pf(-x));
}

__device__ __forceinline__ float red64(float v, float* red) {
    int tid = threadIdx.x;
    #pragma unroll
    for (int o = 16; o > 0; o >>= 1) v += __shfl_xor_sync(0xffffffffu, v, o);
    if ((tid & 31) == 0) red[tid >> 5] = v;
    __syncthreads();
    float r = red[(tid >> 6) * 2] + red[(tid >> 6) * 2 + 1];
    __syncthreads();
    return r;
}

// reduce over aligned groups of 16 lanes
__device__ __forceinline__ float hwred16(float v) {
    v += __shfl_xor_sync(0xffffffffu, v, 8);
    v += __shfl_xor_sync(0xffffffffu, v, 4);
    v += __shfl_xor_sync(0xffffffffu, v, 2);
    v += __shfl_xor_sync(0xffffffffu, v, 1);
    return v;
}

__device__ __forceinline__ float dot4(float4 a, float4 b) {
    return a.x * b.x + a.y * b.y + a.z * b.z + a.w * b.w;
}

// ---------------- phases ----------------

// v = logmap0(proj(mobius_add(proj(mobius_matvec(W, to_hyp(in))), hb)))
template<int IN, int NQ>
__device__ void pre_agg(const float* __restrict__ in,
                        const float* __restrict__ W,
                        const float* HBl, float hbn2v,
                        float* __restrict__ vout, float* SCR, float* XN) {
    constexpr int XHP = IN + 4;
    float* Wt = SCR;             // [IN][68]
    float* xh = SCR + IN * 68;   // [NQ][XHP]
    int tid = threadIdx.x;

    for (int idx = tid; idx < 64 * IN; idx += NTHREADS) {
        int o = idx / IN, k = idx & (IN - 1);
        Wt[k * 68 + o] = W[idx];
    }
    if (tid < NQ * 8) {
        int node = tid >> 3, j = tid & 7;
        constexpr int F4 = IN / 32;   // float4s per thread
        const float4* ur = (const float4*)(in + (size_t)node * IN) + j * F4;
        float4 u[F4];
        float s = 0.f;
        #pragma unroll
        for (int t = 0; t < F4; t++) { u[t] = ur[t]; s += dot4(u[t], u[t]); }
        s += __shfl_xor_sync(0xffffffffu, s, 4);
        s += __shfl_xor_sync(0xffffffffu, s, 2);
        s += __shfl_xor_sync(0xffffffffu, s, 1);
        float un = fmaxf(sqrtf(s), MIN_NORM);
        float tu = tanhf(un);
        float s0 = tu / un, xn = tu;
        if (tu > MAXN) { s0 *= MAXN / tu; xn = MAXN; }
        float4* xrow = (float4*)(xh + node * XHP) + j * F4;
        #pragma unroll
        for (int t = 0; t < F4; t++)
            xrow[t] = make_float4(u[t].x * s0, u[t].y * s0, u[t].z * s0, u[t].w * s0);
        if (j == 0) XN[node] = xn;
    }
    __syncthreads();

    constexpr int NPT = (NQ == 64) ? 2 : 1;
    int grp = tid >> 4, d4 = (tid & 15) << 2;
    int n0 = grp * NPT;
    bool act = n0 < NQ;
    if (!act) n0 = 0;
    float4 acc[NPT];
    #pragma unroll
    for (int n = 0; n < NPT; n++) acc[n] = make_float4(0.f, 0.f, 0.f, 0.f);
    #pragma unroll 8
    for (int k = 0; k < IN; k++) {
        float4 w4 = *(const float4*)(Wt + k * 68 + d4);
        #pragma unroll
        for (int n = 0; n < NPT; n++) {
            float xv = xh[(n0 + n) * XHP + k];
            acc[n].x += xv * w4.x; acc[n].y += xv * w4.y;
            acc[n].z += xv * w4.z; acc[n].w += xv * w4.w;
        }
    }
    float4 hb4 = *(const float4*)(HBl + d4);
    #pragma unroll
    for (int n = 0; n < NPT; n++) {
        int node = n0 + n;
        float4 mx4 = acc[n];
        float mxn = fmaxf(sqrtf(hwred16(dot4(mx4, mx4))), MIN_NORM);
        float xnv = XN[node];
        float qv = mxn / xnv * artanh_f(xnv);
        float tq = tanhf(qv);
        float s1 = tq / mxn, hn = tq;
        if (tq > MAXN) { s1 *= MAXN / tq; hn = MAXN; }
        float4 hv = make_float4(mx4.x * s1, mx4.y * s1, mx4.z * s1, mx4.w * s1);
        float xy = hwred16(dot4(hv, hb4));
        float x2 = hn * hn, y2 = hbn2v;
        float ca = 1.f + 2.f * xy + y2, cb = 1.f - x2;
        float den = fmaxf(1.f + 2.f * xy + x2 * y2, MIN_NORM);
        float4 m = make_float4((ca * hv.x + cb * hb4.x) / den, (ca * hv.y + cb * hb4.y) / den,
                               (ca * hv.z + cb * hb4.z) / den, (ca * hv.w + cb * hb4.w) / den);
        float mn = fmaxf(sqrtf(hwred16(dot4(m, m))), MIN_NORM);
        float s2 = 1.f, pn = mn;
        if (mn > MAXN) { s2 = MAXN / mn; pn = MAXN; }
        float lf = artanh_f(pn) / pn * s2;
        if (act)
            *(float4*)(vout + (size_t)node * 64 + d4) =
                make_float4(m.x * lf, m.y * lf, m.z * lf, m.w * lf);
    }
}

// adj@v -> nonlinear chain -> t; also writes dis (quarter rows)
template<int NPGc>
__device__ void agg(const float* __restrict__ adjg, int q,
                    const float* __restrict__ vg, float* __restrict__ tg,
                    float* __restrict__ disg, float* SCR) {
    constexpr int R = NPGc / 4;
    constexpr int AP = NPGc + 4;
    constexpr int RPT = (R == 64) ? 2 : 1;
    float* v_s = SCR;
    float* a_s = SCR + NPGc * 64;
    int tid = threadIdx.x;
    int rowb = q * R;

    const float4* vg4 = (const float4*)vg;
    float4* v_s4 = (float4*)v_s;
    #pragma unroll 4
    for (int i = tid; i < NPGc * 16; i += NTHREADS) v_s4[i] = vg4[i];
    const float4* ag4 = (const float4*)(adjg + (size_t)rowb * NPGc);
    #pragma unroll 4
    for (int i = tid; i < R * NPGc / 4; i += NTHREADS) {
        int r = i / (NPGc / 4), k4 = i - r * (NPGc / 4);
        *(float4*)(a_s + r * AP + (k4 << 2)) = ag4[i];
    }
    __syncthreads();

    // degree (per-warp)
    {
        constexpr int RPW = R / 16;
        int w = tid >> 5, lane = tid & 31;
        #pragma unroll
        for (int rr = 0; rr < RPW; rr++) {
            int r = w * RPW + rr;
            if (r < R) {
                float s = 0.f;
                #pragma unroll 4
                for (int k = lane; k < NPGc; k += 32) s += a_s[r * AP + k];
                #pragma unroll
                for (int o = 16; o > 0; o >>= 1) s += __shfl_xor_sync(0xffffffffu, s, o);
                if (lane == 0) disg[rowb + r] = (s > 0.f) ? (1.f / sqrtf(s)) : 0.f;
            }
        }
    }

    int grp = tid >> 4, d4 = (tid & 15) << 2;
    int r0 = grp * RPT;
    bool act = r0 < R;
    if (!act) r0 = 0;
    float4 acc[RPT];
    #pragma unroll
    for (int n = 0; n < RPT; n++) acc[n] = make_float4(0.f, 0.f, 0.f, 0.f);
    #pragma unroll 8
    for (int k = 0; k < NPGc; k++) {
        float4 v4 = *(const float4*)(v_s + k * 64 + d4);
        #pragma unroll
        for (int n = 0; n < RPT; n++) {
            float a = a_s[(r0 + n) * AP + k];
            acc[n].x += a * v4.x; acc[n].y += a * v4.y;
            acc[n].z += a * v4.z; acc[n].w += a * v4.w;
        }
    }
    #pragma unroll
    for (int n = 0; n < RPT; n++) {
        float4 y = acc[n];
        float an = fmaxf(sqrtf(hwred16(dot4(y, y))), MIN_NORM);
        float ta = tanhf(an);
        float s1 = ta / an, hn = ta;
        if (ta > MAXN) { s1 *= MAXN / ta; hn = MAXN; }
        float lf = artanh_f(hn) / hn * s1;
        float4 rr = make_float4(fmaxf(y.x * lf, 0.f), fmaxf(y.y * lf, 0.f),
                                fmaxf(y.z * lf, 0.f), fmaxf(y.w * lf, 0.f));
        float rn = fmaxf(sqrtf(hwred16(dot4(rr, rr))), MIN_NORM);
        float tr = tanhf(rn);
        float s2 = tr / rn, en = tr;
        if (tr > MAXN) { s2 *= MAXN / tr; en = MAXN; }
        float tf = artanh_f(en) / en * s2;
        if (act)
            *(float4*)(tg + (size_t)(rowb + r0 + n) * 64 + d4) =
                make_float4(rr.x * tf, rr.y * tf, rr.z * tf, rr.w * tf);
    }
}

// score[i] = sum_d | t[i][d] - dis[i]*(adj@(dis*t))[i][d] |
template<int NPGc>
__device__ void score_ph(const float* __restrict__ adjg, int q,
                         const float* __restrict__ tg, const float* __restrict__ disg,
                         float* __restrict__ scoreg, float* SCR) {
    constexpr int R = NPGc / 4;
    constexpr int AP = NPGc + 4;
    constexpr int RPT = (R == 64) ? 2 : 1;
    float* v_s = SCR;
    float* a_s = SCR + NPGc * 64;
    int tid = threadIdx.x;
    int rowb = q * R;

    const float4* tg4 = (const float4*)tg;
    float4* v_s4 = (float4*)v_s;
    #pragma unroll 4
    for (int i = tid; i < NPGc * 16; i += NTHREADS) {
        float4 t4 = tg4[i];
        float dk = disg[i >> 4];
        v_s4[i] = make_float4(t4.x * dk, t4.y * dk, t4.z * dk, t4.w * dk);
    }
    const float4* ag4 = (const float4*)(adjg + (size_t)rowb * NPGc);
    #pragma unroll 4
    for (int i = tid; i < R * NPGc / 4; i += NTHREADS) {
        int r = i / (NPGc / 4), k4 = i - r * (NPGc / 4);
        *(float4*)(a_s + r * AP + (k4 << 2)) = ag4[i];
    }
    __syncthreads();

    int grp = tid >> 4, d4 = (tid & 15) << 2;
    int r0 = grp * RPT;
    bool act = r0 < R;
    if (!act) r0 = 0;
    float4 acc[RPT];
    #pragma unroll
    for (int n = 0; n < RPT; n++) acc[n] = make_float4(0.f, 0.f, 0.f, 0.f);
    #pragma unroll 8
    for (int k = 0; k < NPGc; k++) {
        float4 v4 = *(const float4*)(v_s + k * 64 + d4);
        #pragma unroll
        for (int n = 0; n < RPT; n++) {
            float a = a_s[(r0 + n) * AP + k];
            acc[n].x += a * v4.x; acc[n].y += a * v4.y;
            acc[n].z += a * v4.z; acc[n].w += a * v4.w;
        }
    }
    #pragma unroll
    for (int n = 0; n < RPT; n++) {
        int r = rowb + r0 + n;
        float disr = disg[r];
        float4 t4 = *(const float4*)(tg + (size_t)r * 64 + d4);
        float sc = hwred16(fabsf(t4.x - disr * acc[n].x) + fabsf(t4.y - disr * acc[n].y) +
                           fabsf(t4.z - disr * acc[n].z) + fabsf(t4.w - disr * acc[n].w));
        if (act && (tid & 15) == 0) scoreg[r] = sc;
    }
}

// bitonic sort, descending, ties -> smaller index first
__device__ void topk(int n, int kk, const float* __restrict__ scoreg,
                     float* SORTS, int* SORTID, int* SELS, float* VALS) {
    int tid = threadIdx.x;
    if (tid < n) { SORTS[tid] = scoreg[tid]; SORTID[tid] = tid; }
    __syncthreads();
    for (int ksz = 2; ksz <= n; ksz <<= 1)
        for (int j = ksz >> 1; j > 0; j >>= 1) {
            if (tid < n) {
                int ixj = tid ^ j;
                if (ixj > tid) {
                    bool asc = (tid & ksz) == 0;
                    float si = SORTS[tid], sj = SORTS[ixj];
                    int ii = SORTID[tid], ij = SORTID[ixj];
                    bool after = (si < sj) || (si == sj && ii > ij);
                    if (after == asc) {
                        SORTS[tid] = sj; SORTS[ixj] = si;
                        SORTID[tid] = ij; SORTID[ixj] = ii;
                    }
                }
            }
            __syncthreads();
        }
    if (tid < kk) { SELS[tid] = SORTID[tid]; VALS[tid] = SORTS[tid]; }
    __syncthreads();
}

// pool ALL kk rows redundantly (identical values per CTA); a1/a2 -> smem
__device__ void pool(int kk, const float* __restrict__ tg, const float* __restrict__ att,
                     float* __restrict__ tBg, float* SA1, float* SA2,
                     const int* SELS, const float* VALS) {
    int tid = threadIdx.x, hw = tid >> 4, l4 = (tid & 15) << 2;
    float4 at1 = *(const float4*)(att + l4);
    float4 at2 = *(const float4*)(att + 64 + l4);
    for (int it = 0; it < (kk >> 5); it++) {
        int i = (it << 5) + hw;
        int li = SELS[i];
        float tn = tanhf(VALS[i]);
        float4 xv = *(const float4*)(tg + (size_t)li * 64 + l4);
        xv = make_float4(xv.x * tn, xv.y * tn, xv.z * tn, xv.w * tn);
        *(float4*)(tBg + (size_t)i * 64 + l4) = xv;
        float r1 = hwred16(dot4(xv, at1));
        float r2 = hwred16(dot4(xv, at2));
        if ((tid & 15) == 0) { SA1[i] = r1; SA2[i] = r2; }
    }
    __syncthreads();
}

template<int KK>
__device__ void new_adj(const float* __restrict__ adjsrc, int npg, int q,
                        const float* SA1, const float* SA2, const int* SELS,
                        float* __restrict__ adjdst) {
    int tid = threadIdx.x;
    constexpr int QN = KK / 4;
    for (int idx = tid; idx < QN * KK; idx += NTHREADS) {
        int il = idx / KK;
        int i = q * QN + il;
        int j = idx & (KK - 1);
        float e = SA1[i] + SA2[j];
        adjdst[(size_t)i * KK + j] =
            fmaxf(e, 0.f) + adjsrc[(size_t)SELS[i] * npg + SELS[j]];
    }
}

__device__ void readout(const float* __restrict__ tg, int kk, float* XR) {
    int tid = threadIdx.x;
    if (tid < 64) {
        float mx = -INFINITY, sm = 0.f;
        for (int i = 0; i < kk; i++) {
            float v = tg[(size_t)i * 64 + tid];
            mx = fmaxf(mx, v); sm += v;
        }
        XR[tid] = mx; XR[64 + tid] = sm / (float)kk;
    }
    __syncthreads();
}

// ---------------- megakernel ----------------
extern __shared__ float sm[];

__global__ void __cluster_dims__(4, 1, 1) __launch_bounds__(NTHREADS, 1)
mega_kernel(const float* __restrict__ x, const int* __restrict__ ei, int E,
            const float* __restrict__ W1, const float* __restrict__ b1,
            const float* __restrict__ W2, const float* __restrict__ b2,
            const float* __restrict__ W3, const float* __restrict__ b3,
            const float* __restrict__ att1, const float* __restrict__ att2,
            const float* __restrict__ lw1, const float* __restrict__ lb1,
            const float* __restrict__ lw2, const float* __restrict__ lb2,
            const float* __restrict__ lw3, const float* __restrict__ lb3,
            float* __restrict__ out) {
    float* HB = sm + SM_HB;
    float* HBN2 = sm + SM_HBN2;
    float* RED = sm + SM_RED;
    float* SORTS = sm + SM_SORTS;
    int*   SORTID = (int*)(sm + SM_SORTID);
    int*   SELS = (int*)(sm + SM_SELS);
    float* VALS = sm + SM_VALS;
    float* SA1 = sm + SM_SA1;
    float* SA2 = sm + SM_SA2;
    float* X1R = sm + SM_X1R;
    float* X2R = sm + SM_X2R;
    float* X3R = sm + SM_X3R;
    float* XN = sm + SM_XN;
    float* MLP0 = sm + SM_MLP0;
    float* MLP1 = sm + SM_MLP1;
    float* MLP2 = sm + SM_MLP2;
    float* SCR = sm + SM_SCR;

    int g = blockIdx.x >> 2, q = blockIdx.x & 3, tid = threadIdx.x;

    float* adj1g = g_adj1 + (size_t)g * 256 * 256;
    float* adj2g = g_adj2 + (size_t)g * 128 * 128;
    float* adj3g = g_adj3 + (size_t)g * 64 * 64;
    float* vg = g_v + (size_t)g * GS * 64;
    float* tAg = g_tA + (size_t)g * GS * 64;
    float* tBg = g_tB + (size_t)g * GS * 64;
    float* disg = g_dis + (size_t)g * GS;
    float* scoreg = g_score + (size_t)g * GS;

    // hb = proj(expmap0(b_l))
    {
        int l = tid >> 6, d = tid & 63;
        float u = (l < 3) ? ((l == 0 ? b1 : (l == 1 ? b2 : b3))[d]) : 0.f;
        float un2 = red64(u * u, RED);
        if (l < 3) {
            float un = fmaxf(sqrtf(un2), MIN_NORM);
            float tu = tanhf(un);
            float s0 = tu / un, pn = tu;
            if (tu > MAXN) { s0 *= MAXN / tu; pn = MAXN; }
            HB[l * 64 + d] = u * s0;
            if (d == 0) HBN2[l] = pn * pn;
        }
    }
    __syncthreads();

    // sx (quarter)
    {
        int node = tid >> 3, j = tid & 7;
        int gn = g * NPG + q * 64 + node;
        const float4* xr = (const float4*)(x + (size_t)gn * 128 + j * 16);
        float s = 0.f;
        #pragma unroll
        for (int p = 0; p < 4; p++) { float4 v4 = xr[p]; s += v4.x + v4.y + v4.z + v4.w; }
        s += __shfl_xor_sync(0xffffffffu, s, 4);
        s += __shfl_xor_sync(0xffffffffu, s, 2);
        s += __shfl_xor_sync(0xffffffffu, s, 1);
        if (j == 0) g_sx[gn] = s;
    }
    // zero adj1 quarter
    {
        float4* dst = (float4*)(adj1g + (size_t)q * 64 * 256);
        #pragma unroll 4
        for (int i = tid; i < 64 * 256 / 4; i += NTHREADS)
            dst[i] = make_float4(0.f, 0.f, 0.f, 0.f);
    }
    pre_agg<128, 64>(x + (size_t)(g * NPG + q * 64) * 128, W1, HB, HBN2[0],
                     vg + (size_t)(q * 64) * 64, SCR, XN);
    CSYNC();

    // scatter quarter share of this graph's edges
    {
        int Eg = E / NB;
        for (int t = q + 4 * tid; t < Eg; t += 4 * NTHREADS) {
            int e = g * Eg + t;
            int r = ei[e], c = ei[E + e];
            adj1g[(size_t)(r & 255) * 256 + (c & 255)] = 0.5f * (g_sx[r] + g_sx[c]);
        }
    }
    CSYNC();

    agg<256>(adj1g, q, vg, tAg, disg, SCR);
    CSYNC();
    score_ph<256>(adj1g, q, tAg, disg, scoreg, SCR);
    CSYNC();
    topk(256, 128, scoreg, SORTS, SORTID, SELS, VALS);
    pool(128, tAg, att1, tBg, SA1, SA2, SELS, VALS);
    new_adj<128>(adj1g, 256, q, SA1, SA2, SELS, adj2g);
    readout(tBg, 128, X1R);
    pre_agg<64, 32>(tBg + (size_t)(q * 32) * 64, W2, HB + 64, HBN2[1],
                    vg + (size_t)(q * 32) * 64, SCR, XN);
    CSYNC();

    agg<128>(adj2g, q, vg, tAg, disg, SCR);
    CSYNC();
    score_ph<128>(adj2g, q, tAg, disg, scoreg, SCR);
    CSYNC();
    topk(128, 64, scoreg, SORTS, SORTID, SELS, VALS);
    pool(64, tAg, att2, tBg, SA1, SA2, SELS, VALS);
    new_adj<64>(adj2g, 128, q, SA1, SA2, SELS, adj3g);
    readout(tBg, 64, X2R);
    pre_agg<64, 16>(tBg + (size_t)(q * 16) * 64, W3, HB + 128, HBN2[2],
                    vg + (size_t)(q * 16) * 64, SCR, XN);
    CSYNC();

    agg<64>(adj3g, q, vg, tAg, disg, SCR);
    CSYNC();
    readout(tAg, 64, X3R);

    // MLP head (redundant per CTA; q==0 writes)
    if (tid < 128)
        MLP0[tid] = fmaxf(X1R[tid], 0.f) + fmaxf(X2R[tid], 0.f) + fmaxf(X3R[tid], 0.f);
    __syncthreads();
    if (tid < 64) {
        float acc = lb1[tid];
        #pragma unroll 8
        for (int k = 0; k < 128; k++) acc += lw1[tid * 128 + k] * MLP0[k];
        MLP1[tid] = fmaxf(acc, 0.f);
    }
    __syncthreads();
    if (tid < 32) {
        float acc = lb2[tid];
        #pragma unroll 8
        for (int k = 0; k < 64; k++) acc += lw2[tid * 64 + k] * MLP1[k];
        MLP2[tid] = fmaxf(acc, 0.f);
    }
    __syncthreads();
    if (tid == 0 && q == 0) {
        float l[NCLASS];
        float m = -INFINITY;
        for (int j = 0; j < NCLASS; j++) {
            float acc = lb3[j];
            for (int k = 0; k < 32; k++) acc += lw3[j * 32 + k] * MLP2[k];
            l[j] = acc;
            m = fmaxf(m, acc);
        }
        float s = 0.f;
        for (int j = 0; j < NCLASS; j++) s += expf(l[j] - m);
        float lse = m + logf(s);
        for (int j = 0; j < NCLASS; j++) out[g * NCLASS + j] = l[j] - lse;
    }
}

// ---------------- launch ----------------
extern "C" void kernel_launch(void* const* d_in, const int* in_sizes, int n_in,
                              void* d_out, int out_size) {
    const float* x    = (const float*)d_in[0];
    const int*   ei   = (const int*)d_in[1];
    const float* W1   = (const float*)d_in[2];
    const float* b1   = (const float*)d_in[3];
    const float* W2   = (const float*)d_in[4];
    const float* b2   = (const float*)d_in[5];
    const float* W3   = (const float*)d_in[6];
    const float* b3   = (const float*)d_in[7];
    const float* att1 = (const float*)d_in[8];
    const float* att2 = (const float*)d_in[9];
    const float* lw1  = (const float*)d_in[10];
    const float* lb1  = (const float*)d_in[11];
    const float* lw2  = (const float*)d_in[12];
    const float* lb2  = (const float*)d_in[13];
    const float* lw3  = (const float*)d_in[14];
    const float* lb3  = (const float*)d_in[15];

    int E = in_sizes[1] / 2;

    cudaFuncSetAttribute(mega_kernel, cudaFuncAttributeMaxDynamicSharedMemorySize, SMEM_BYTES);
    mega_kernel<<<GRID, NTHREADS, SMEM_BYTES>>>(
        x, ei, E, W1, b1, W2, b2, W3, b3, att1, att2,
        lw1, lb1, lw2, lb2, lw3, lb3, (float*)d_out);
}

// round 6
// speedup vs baseline: 8.2987x; 1.0589x over previous
#include <cuda_runtime.h>
#include <cuda_bf16.h>
#include <math.h>

#define NB    32
#define NPG   256
#define GS    256
#define NCLASS 6
#define MIN_NORM 1e-15f
#define MAXN 0.996f

#define NTHREADS 512
#define GRID     (NB * 4)

typedef unsigned long long u64;

// ---------------- global scratch ----------------
__device__ float g_sx[NB * NPG];
__device__ float g_adj1[NB * 256 * 256];
__device__ float g_adj2[NB * 128 * 128];
__device__ float g_v  [NB * GS * 64];
__device__ float g_tA [NB * GS * 64];
__device__ float g_tB [NB * GS * 64];
__device__ float g_dis[NB * GS];
__device__ float g_score[NB * GS];

// ---------------- smem layout (floats) ----------------
#define SM_HB     0        // 192
#define SM_HBN2   192      // 4
#define SM_RED    196      // 16
#define SM_SORTS  212      // 256
#define SM_SORTID 468      // 256 (int)
#define SM_SELS   724      // 128 (int)
#define SM_VALS   852      // 128
#define SM_SA1    980      // 128
#define SM_SA2    1108     // 128
#define SM_X1R    1236     // 128
#define SM_X2R    1364     // 128
#define SM_X3R    1492     // 128
#define SM_XN     1620     // 64
#define SM_MLP0   1684     // 128
#define SM_MLP1   1812     // 64
#define SM_MLP2   1876     // 32
#define SM_SCR    1920
// SCR union (floats, relative to SCR):
//   L1 agg/score: v_s [0,16384) + a_s [16384, 33024)          (AP=260)
//   L2 agg/score: v_s [0,8192)  + a_s [16384, 16384+32*132)   (AP=132, staged from g_adj2)
//   L3 agg:       v_s [0,4096)  + a3_s [A3OFF, A3OFF+16*68)   (AP=68, filled by new_adj L3)
//   pre_agg L1: Wt [0,8704) + xh [8704,17408); L2/L3 smaller
//   readout scratch: [0,1024)
#define A_L12  (256 * 64)   // 16384
#define A3OFF  22000        // clear of pre_agg L3 (<=6528) and L2 a_s end (20608)
#define SM_TOTALF (1920 + 33024)
#define SMEM_BYTES (SM_TOTALF * 4)

#define CSYNC() do { asm volatile("barrier.cluster.arrive.aligned;" ::: "memory"); \
                     asm volatile("barrier.cluster.wait.aligned;"   ::: "memory"); } while (0)

// ---------------- helpers ----------------
__device__ __forceinline__ float artanh_f(float x) {
    x = fminf(fmaxf(x, -1.0f + 1e-7f), 1.0f - 1e-7f);
    return 0.5f * (log1pf(x) - log1pf(-x));
}
__device__ __forceinline__ float wred32(float v) {
    #pragma unroll
    for (int o = 16; o > 0; o >>= 1) v += __shfl_xor_sync(0xffffffffu, v, o);
    return v;
}
__device__ __forceinline__ float hwred16(float v) {
    v += __shfl_xor_sync(0xffffffffu, v, 8);
    v += __shfl_xor_sync(0xffffffffu, v, 4);
    v += __shfl_xor_sync(0xffffffffu, v, 2);
    v += __shfl_xor_sync(0xffffffffu, v, 1);
    return v;
}
__device__ __forceinline__ float red64(float v, float* red) {
    int tid = threadIdx.x;
    #pragma unroll
    for (int o = 16; o > 0; o >>= 1) v += __shfl_xor_sync(0xffffffffu, v, o);
    if ((tid & 31) == 0) red[tid >> 5] = v;
    __syncthreads();
    float r = red[(tid >> 6) * 2] + red[(tid >> 6) * 2 + 1];
    __syncthreads();
    return r;
}
__device__ __forceinline__ float dot4(float4 a, float4 b) {
    return a.x * b.x + a.y * b.y + a.z * b.z + a.w * b.w;
}
__device__ __forceinline__ u64 pk2(float a) {
    u64 r; asm("mov.b64 %0,{%1,%1};" : "=l"(r) : "f"(a)); return r;
}
__device__ __forceinline__ u64 f2fma(u64 a, u64 b, u64 c) {
    u64 d; asm("fma.rn.f32x2 %0,%1,%2,%3;" : "=l"(d) : "l"(a), "l"(b), "l"(c)); return d;
}
__device__ __forceinline__ float2 upk(u64 a) {
    float2 f; asm("mov.b64 {%0,%1},%2;" : "=f"(f.x), "=f"(f.y) : "l"(a)); return f;
}

// ---------------- phases ----------------

template<int IN, int NQ>
__device__ void pre_agg(const float* __restrict__ in,
                        const float* __restrict__ W,
                        const float* HBl, float hbn2v,
                        float* __restrict__ vout, float* SCR, float* XN) {
    constexpr int XHP = IN + 8;
    constexpr int NR = NQ / 16;
    float* Wt = SCR;
    float* xh = SCR + IN * 68;
    int tid = threadIdx.x, w = tid >> 5, lane = tid & 31;

    for (int idx = tid; idx < 64 * IN; idx += NTHREADS) {
        int o = idx / IN, k = idx & (IN - 1);
        Wt[k * 68 + o] = W[idx];
    }
    if (tid < NQ * 8) {
        int node = tid >> 3, j = tid & 7;
        constexpr int F4 = IN / 32;
        const float4* ur = (const float4*)(in + (size_t)node * IN) + j * F4;
        float4 u[F4];
        float s = 0.f;
        #pragma unroll
        for (int t = 0; t < F4; t++) { u[t] = ur[t]; s += dot4(u[t], u[t]); }
        s += __shfl_xor_sync(0xffffffffu, s, 4);
        s += __shfl_xor_sync(0xffffffffu, s, 2);
        s += __shfl_xor_sync(0xffffffffu, s, 1);
        float un = fmaxf(sqrtf(s), MIN_NORM);
        float tu = tanhf(un);
        float s0 = tu / un, xn = tu;
        if (tu > MAXN) { s0 *= MAXN / tu; xn = MAXN; }
        float4* xrow = (float4*)(xh + node * XHP) + j * F4;
        #pragma unroll
        for (int t = 0; t < F4; t++)
            xrow[t] = make_float4(u[t].x * s0, u[t].y * s0, u[t].z * s0, u[t].w * s0);
        if (j == 0) XN[node] = xn;
    }
    __syncthreads();

    u64 acc[NR];
    #pragma unroll
    for (int r = 0; r < NR; r++) acc[r] = 0ull;
    #pragma unroll 2
    for (int k0 = 0; k0 < IN; k0 += 4) {
        float4 a[NR];
        #pragma unroll
        for (int r = 0; r < NR; r++)
            a[r] = *(const float4*)(xh + (w * NR + r) * XHP + k0);
        u64 vv[4];
        #pragma unroll
        for (int j = 0; j < 4; j++)
            vv[j] = *(const u64*)(Wt + (k0 + j) * 68 + 2 * lane);
        #pragma unroll
        for (int r = 0; r < NR; r++) {
            acc[r] = f2fma(pk2(a[r].x), vv[0], acc[r]);
            acc[r] = f2fma(pk2(a[r].y), vv[1], acc[r]);
            acc[r] = f2fma(pk2(a[r].z), vv[2], acc[r]);
            acc[r] = f2fma(pk2(a[r].w), vv[3], acc[r]);
        }
    }
    float2 hb2 = *(const float2*)(HBl + 2 * lane);
    #pragma unroll
    for (int r = 0; r < NR; r++) {
        int node = w * NR + r;
        float2 mx = upk(acc[r]);
        float mxn = fmaxf(sqrtf(wred32(mx.x * mx.x + mx.y * mx.y)), MIN_NORM);
        float xnv = XN[node];
        float qv = mxn / xnv * artanh_f(xnv);
        float tq = tanhf(qv);
        float s1 = tq / mxn, hn = tq;
        if (tq > MAXN) { s1 *= MAXN / tq; hn = MAXN; }
        float2 hv = make_float2(mx.x * s1, mx.y * s1);
        float xy = wred32(hv.x * hb2.x + hv.y * hb2.y);
        float x2 = hn * hn, y2 = hbn2v;
        float ca = 1.f + 2.f * xy + y2, cb = 1.f - x2;
        float den = fmaxf(1.f + 2.f * xy + x2 * y2, MIN_NORM);
        float2 m = make_float2((ca * hv.x + cb * hb2.x) / den,
                               (ca * hv.y + cb * hb2.y) / den);
        float mn = fmaxf(sqrtf(wred32(m.x * m.x + m.y * m.y)), MIN_NORM);
        float s2 = 1.f, pn = mn;
        if (mn > MAXN) { s2 = MAXN / mn; pn = MAXN; }
        float lf = artanh_f(pn) / pn * s2;
        *(float2*)(vout + (size_t)node * 64 + 2 * lane) =
            make_float2(m.x * lf, m.y * lf);
    }
}

template<int NPGc, int A_OFF, bool STAGE_A>
__device__ void agg(const float* __restrict__ adjg, int q,
                    const float* __restrict__ vg, float* __restrict__ tg,
                    float* __restrict__ disg, float* SCR) {
    constexpr int R = NPGc / 4;
    constexpr int AP = NPGc + 4;
    constexpr int NR = R / 16;
    float* v_s = SCR;
    float* a_s = SCR + A_OFF;
    int tid = threadIdx.x, w = tid >> 5, lane = tid & 31;
    int rowb = q * R;

    { const float4* vg4 = (const float4*)vg; float4* v_s4 = (float4*)v_s;
      #pragma unroll 4
      for (int i = tid; i < NPGc * 16; i += NTHREADS) v_s4[i] = vg4[i]; }
    if (STAGE_A) {
        const float4* ag4 = (const float4*)(adjg + (size_t)rowb * NPGc);
        #pragma unroll 4
        for (int i = tid; i < R * NPGc / 4; i += NTHREADS) {
            int r = i / (NPGc / 4), k4 = i - r * (NPGc / 4);
            *(float4*)(a_s + r * AP + (k4 << 2)) = ag4[i];
        }
    }
    __syncthreads();

    #pragma unroll
    for (int rr = 0; rr < NR; rr++) {
        int r = w * NR + rr;
        float s = 0.f;
        #pragma unroll 4
        for (int k = lane; k < NPGc; k += 32) s += a_s[r * AP + k];
        s = wred32(s);
        if (lane == 0) disg[rowb + r] = (s > 0.f) ? (1.f / sqrtf(s)) : 0.f;
    }

    u64 acc[NR];
    #pragma unroll
    for (int r = 0; r < NR; r++) acc[r] = 0ull;
    #pragma unroll 2
    for (int k0 = 0; k0 < NPGc; k0 += 4) {
        float4 a[NR];
        #pragma unroll
        for (int r = 0; r < NR; r++)
            a[r] = *(const float4*)(a_s + (w * NR + r) * AP + k0);
        u64 vv[4];
        #pragma unroll
        for (int j = 0; j < 4; j++)
            vv[j] = *(const u64*)(v_s + (k0 + j) * 64 + 2 * lane);
        #pragma unroll
        for (int r = 0; r < NR; r++) {
            acc[r] = f2fma(pk2(a[r].x), vv[0], acc[r]);
            acc[r] = f2fma(pk2(a[r].y), vv[1], acc[r]);
            acc[r] = f2fma(pk2(a[r].z), vv[2], acc[r]);
            acc[r] = f2fma(pk2(a[r].w), vv[3], acc[r]);
        }
    }
    #pragma unroll
    for (int r = 0; r < NR; r++) {
        float2 y = upk(acc[r]);
        float an = fmaxf(sqrtf(wred32(y.x * y.x + y.y * y.y)), MIN_NORM);
        float ta = tanhf(an);
        float s1 = ta / an, hn = ta;
        if (ta > MAXN) { s1 *= MAXN / ta; hn = MAXN; }
        float lf = artanh_f(hn) / hn * s1;
        float2 rr2 = make_float2(fmaxf(y.x * lf, 0.f), fmaxf(y.y * lf, 0.f));
        float rn = fmaxf(sqrtf(wred32(rr2.x * rr2.x + rr2.y * rr2.y)), MIN_NORM);
        float tr = tanhf(rn);
        float s2 = tr / rn, en = tr;
        if (tr > MAXN) { s2 *= MAXN / tr; en = MAXN; }
        float tf = artanh_f(en) / en * s2;
        *(float2*)(tg + (size_t)(rowb + w * NR + r) * 64 + 2 * lane) =
            make_float2(rr2.x * tf, rr2.y * tf);
    }
}

template<int NPGc, int A_OFF>
__device__ void score_ph(int q, const float* __restrict__ tg,
                         const float* __restrict__ disg,
                         float* __restrict__ scoreg, float* SCR) {
    constexpr int R = NPGc / 4;
    constexpr int AP = NPGc + 4;
    constexpr int NR = R / 16;
    float* v_s = SCR;
    float* a_s = SCR + A_OFF;
    int tid = threadIdx.x, w = tid >> 5, lane = tid & 31;
    int rowb = q * R;

    { const float4* tg4 = (const float4*)tg; float4* v_s4 = (float4*)v_s;
      #pragma unroll 4
      for (int i = tid; i < NPGc * 16; i += NTHREADS) {
          float4 t4 = tg4[i];
          float dk = disg[i >> 4];
          v_s4[i] = make_float4(t4.x * dk, t4.y * dk, t4.z * dk, t4.w * dk);
      } }
    __syncthreads();

    u64 acc[NR];
    #pragma unroll
    for (int r = 0; r < NR; r++) acc[r] = 0ull;
    #pragma unroll 2
    for (int k0 = 0; k0 < NPGc; k0 += 4) {
        float4 a[NR];
        #pragma unroll
        for (int r = 0; r < NR; r++)
            a[r] = *(const float4*)(a_s + (w * NR + r) * AP + k0);
        u64 vv[4];
        #pragma unroll
        for (int j = 0; j < 4; j++)
            vv[j] = *(const u64*)(v_s + (k0 + j) * 64 + 2 * lane);
        #pragma unroll
        for (int r = 0; r < NR; r++) {
            acc[r] = f2fma(pk2(a[r].x), vv[0], acc[r]);
            acc[r] = f2fma(pk2(a[r].y), vv[1], acc[r]);
            acc[r] = f2fma(pk2(a[r].z), vv[2], acc[r]);
            acc[r] = f2fma(pk2(a[r].w), vv[3], acc[r]);
        }
    }
    #pragma unroll
    for (int r = 0; r < NR; r++) {
        int row = rowb + w * NR + r;
        float2 y = upk(acc[r]);
        float disr = disg[row];
        float2 tv = *(const float2*)(tg + (size_t)row * 64 + 2 * lane);
        float sc = wred32(fabsf(tv.x - disr * y.x) + fabsf(tv.y - disr * y.y));
        if (lane == 0) scoreg[row] = sc;
    }
}

__device__ void topk(int n, int kk, const float* __restrict__ scoreg,
                     float* SORTS, int* SORTID, int* SELS, float* VALS) {
    int tid = threadIdx.x;
    if (tid < n) { SORTS[tid] = scoreg[tid]; SORTID[tid] = tid; }
    __syncthreads();
    for (int ksz = 2; ksz <= n; ksz <<= 1)
        for (int j = ksz >> 1; j > 0; j >>= 1) {
            if (tid < n) {
                int ixj = tid ^ j;
                if (ixj > tid) {
                    bool asc = (tid & ksz) == 0;
                    float si = SORTS[tid], sj = SORTS[ixj];
                    int ii = SORTID[tid], ij = SORTID[ixj];
                    bool after = (si < sj) || (si == sj && ii > ij);
                    if (after == asc) {
                        SORTS[tid] = sj; SORTS[ixj] = si;
                        SORTID[tid] = ij; SORTID[ixj] = ii;
                    }
                }
            }
            __syncthreads();
        }
    if (tid < kk) { SELS[tid] = SORTID[tid]; VALS[tid] = SORTS[tid]; }
    __syncthreads();
}

__device__ void pool(int kk, const float* __restrict__ tg, const float* __restrict__ att,
                     float* __restrict__ tBg, float* SA1, float* SA2,
                     const int* SELS, const float* VALS) {
    int tid = threadIdx.x, hw = tid >> 4, l4 = (tid & 15) << 2;
    float4 at1 = *(const float4*)(att + l4);
    float4 at2 = *(const float4*)(att + 64 + l4);
    for (int it = 0; it < (kk >> 5); it++) {
        int i = (it << 5) + hw;
        int li = SELS[i];
        float tn = tanhf(VALS[i]);
        float4 xv = *(const float4*)(tg + (size_t)li * 64 + l4);
        xv = make_float4(xv.x * tn, xv.y * tn, xv.z * tn, xv.w * tn);
        *(float4*)(tBg + (size_t)i * 64 + l4) = xv;
        float r1 = hwred16(dot4(xv, at1));
        float r2 = hwred16(dot4(xv, at2));
        if ((tid & 15) == 0) { SA1[i] = r1; SA2[i] = r2; }
    }
    __syncthreads();
}

// L2 adjacency -> global (rows gathered cross-CTA later)
template<int KK>
__device__ void new_adj_gl(const float* __restrict__ adjsrc, int npg, int q,
                           const float* SA1, const float* SA2, const int* SELS,
                           float* __restrict__ adjdst) {
    int tid = threadIdx.x;
    constexpr int QN = KK / 4;
    for (int idx = tid; idx < QN * KK; idx += NTHREADS) {
        int il = idx / KK;
        int i = q * QN + il;
        int j = idx & (KK - 1);
        float e = SA1[i] + SA2[j];
        adjdst[(size_t)i * KK + j] =
            fmaxf(e, 0.f) + adjsrc[(size_t)SELS[i] * npg + SELS[j]];
    }
}

// L3 adjacency -> smem (only own quarter rows ever read)
template<int KK>
__device__ void new_adj_sm(const float* __restrict__ adjsrc, int npg, int q,
                           const float* SA1, const float* SA2, const int* SELS,
                           float* a_dst) {
    int tid = threadIdx.x;
    constexpr int QN = KK / 4;
    constexpr int APd = KK + 4;
    for (int idx = tid; idx < QN * KK; idx += NTHREADS) {
        int il = idx / KK;
        int i = q * QN + il;
        int j = idx & (KK - 1);
        float e = SA1[i] + SA2[j];
        a_dst[il * APd + j] =
            fmaxf(e, 0.f) + adjsrc[(size_t)SELS[i] * npg + SELS[j]];
    }
}

__device__ void readout(const float* __restrict__ tg, int kk, float* XR, float* RS) {
    int tid = threadIdx.x;
    int d = tid & 63, grp = tid >> 6;
    float mx = -INFINITY, sm2 = 0.f;
    for (int i = grp; i < kk; i += 8) {
        float v = tg[(size_t)i * 64 + d];
        mx = fmaxf(mx, v); sm2 += v;
    }
    RS[grp * 64 + d] = mx;
    RS[512 + grp * 64 + d] = sm2;
    __syncthreads();
    if (tid < 64) {
        float m = -INFINITY, s = 0.f;
        #pragma unroll
        for (int g2 = 0; g2 < 8; g2++) {
            m = fmaxf(m, RS[g2 * 64 + tid]);
            s += RS[512 + g2 * 64 + tid];
        }
        XR[tid] = m; XR[64 + tid] = s / (float)kk;
    }
    __syncthreads();
}

// ---------------- megakernel ----------------
extern __shared__ float sm[];

__global__ void __cluster_dims__(4, 1, 1) __launch_bounds__(NTHREADS, 1)
mega_kernel(const float* __restrict__ x, const int* __restrict__ ei, int E,
            const float* __restrict__ W1, const float* __restrict__ b1,
            const float* __restrict__ W2, const float* __restrict__ b2,
            const float* __restrict__ W3, const float* __restrict__ b3,
            const float* __restrict__ att1, const float* __restrict__ att2,
            const float* __restrict__ lw1, const float* __restrict__ lb1,
            const float* __restrict__ lw2, const float* __restrict__ lb2,
            const float* __restrict__ lw3, const float* __restrict__ lb3,
            float* __restrict__ out) {
    float* HB = sm + SM_HB;
    float* HBN2 = sm + SM_HBN2;
    float* RED = sm + SM_RED;
    float* SORTS = sm + SM_SORTS;
    int*   SORTID = (int*)(sm + SM_SORTID);
    int*   SELS = (int*)(sm + SM_SELS);
    float* VALS = sm + SM_VALS;
    float* SA1 = sm + SM_SA1;
    float* SA2 = sm + SM_SA2;
    float* X1R = sm + SM_X1R;
    float* X2R = sm + SM_X2R;
    float* X3R = sm + SM_X3R;
    float* XN = sm + SM_XN;
    float* MLP0 = sm + SM_MLP0;
    float* MLP1 = sm + SM_MLP1;
    float* MLP2 = sm + SM_MLP2;
    float* SCR = sm + SM_SCR;

    int g = blockIdx.x >> 2, q = blockIdx.x & 3, tid = threadIdx.x;

    float* adj1g = g_adj1 + (size_t)g * 256 * 256;
    float* adj2g = g_adj2 + (size_t)g * 128 * 128;
    float* vg = g_v + (size_t)g * GS * 64;
    float* tAg = g_tA + (size_t)g * GS * 64;
    float* tBg = g_tB + (size_t)g * GS * 64;
    float* disg = g_dis + (size_t)g * GS;
    float* scoreg = g_score + (size_t)g * GS;

    {
        int l = tid >> 6, d = tid & 63;
        float u = (l < 3) ? ((l == 0 ? b1 : (l == 1 ? b2 : b3))[d]) : 0.f;
        float un2 = red64(u * u, RED);
        if (l < 3) {
            float un = fmaxf(sqrtf(un2), MIN_NORM);
            float tu = tanhf(un);
            float s0 = tu / un, pn = tu;
            if (tu > MAXN) { s0 *= MAXN / tu; pn = MAXN; }
            HB[l * 64 + d] = u * s0;
            if (d == 0) HBN2[l] = pn * pn;
        }
    }
    __syncthreads();

    {
        int node = tid >> 3, j = tid & 7;
        int gn = g * NPG + q * 64 + node;
        const float4* xr = (const float4*)(x + (size_t)gn * 128 + j * 16);
        float s = 0.f;
        #pragma unroll
        for (int p = 0; p < 4; p++) { float4 v4 = xr[p]; s += v4.x + v4.y + v4.z + v4.w; }
        s += __shfl_xor_sync(0xffffffffu, s, 4);
        s += __shfl_xor_sync(0xffffffffu, s, 2);
        s += __shfl_xor_sync(0xffffffffu, s, 1);
        if (j == 0) g_sx[gn] = s;
    }
    {
        float4* dst = (float4*)(adj1g + (size_t)q * 64 * 256);
        #pragma unroll 4
        for (int i = tid; i < 64 * 256 / 4; i += NTHREADS)
            dst[i] = make_float4(0.f, 0.f, 0.f, 0.f);
    }
    pre_agg<128, 64>(x + (size_t)(g * NPG + q * 64) * 128, W1, HB, HBN2[0],
                     vg + (size_t)(q * 64) * 64, SCR, XN);
    CSYNC();

    {
        int Eg = E / NB;
        for (int t = q + 4 * tid; t < Eg; t += 4 * NTHREADS) {
            int e = g * Eg + t;
            int r = ei[e], c = ei[E + e];
            adj1g[(size_t)(r & 255) * 256 + (c & 255)] = 0.5f * (g_sx[r] + g_sx[c]);
        }
    }
    CSYNC();

    agg<256, A_L12, true>(adj1g, q, vg, tAg, disg, SCR);
    CSYNC();
    score_ph<256, A_L12>(q, tAg, disg, scoreg, SCR);
    CSYNC();
    topk(256, 128, scoreg, SORTS, SORTID, SELS, VALS);
    pool(128, tAg, att1, tBg, SA1, SA2, SELS, VALS);
    new_adj_gl<128>(adj1g, 256, q, SA1, SA2, SELS, adj2g);
    readout(tBg, 128, X1R, SCR);
    pre_agg<64, 32>(tBg + (size_t)(q * 32) * 64, W2, HB + 64, HBN2[1],
                    vg + (size_t)(q * 32) * 64, SCR, XN);
    CSYNC();

    agg<128, A_L12, true>(adj2g, q, vg, tAg, disg, SCR);
    CSYNC();
    score_ph<128, A_L12>(q, tAg, disg, scoreg, SCR);
    CSYNC();
    topk(128, 64, scoreg, SORTS, SORTID, SELS, VALS);
    pool(64, tAg, att2, tBg, SA1, SA2, SELS, VALS);
    new_adj_sm<64>(adj2g, 128, q, SA1, SA2, SELS, SCR + A3OFF);
    readout(tBg, 64, X2R, SCR);
    pre_agg<64, 16>(tBg + (size_t)(q * 16) * 64, W3, HB + 128, HBN2[2],
                    vg + (size_t)(q * 16) * 64, SCR, XN);
    CSYNC();

    agg<64, A3OFF, false>(nullptr, q, vg, tAg, disg, SCR);
    CSYNC();
    readout(tAg, 64, X3R, SCR);

    if (tid < 128)
        MLP0[tid] = fmaxf(X1R[tid], 0.f) + fmaxf(X2R[tid], 0.f) + fmaxf(X3R[tid], 0.f);
    __syncthreads();
    if (tid < 64) {
        float acc = lb1[tid];
        #pragma unroll 8
        for (int k = 0; k < 128; k++) acc += lw1[tid * 128 + k] * MLP0[k];
        MLP1[tid] = fmaxf(acc, 0.f);
    }
    __syncthreads();
    if (tid < 32) {
        float acc = lb2[tid];
        #pragma unroll 8
        for (int k = 0; k < 64; k++) acc += lw2[tid * 64 + k] * MLP1[k];
        MLP2[tid] = fmaxf(acc, 0.f);
    }
    __syncthreads();
    if (tid == 0 && q == 0) {
        float l[NCLASS];
        float m = -INFINITY;
        for (int j = 0; j < NCLASS; j++) {
            float acc = lb3[j];
            for (int k = 0; k < 32; k++) acc += lw3[j * 32 + k] * MLP2[k];
            l[j] = acc;
            m = fmaxf(m, acc);
        }
        float s = 0.f;
        for (int j = 0; j < NCLASS; j++) s += expf(l[j] - m);
        float lse = m + logf(s);
        for (int j = 0; j < NCLASS; j++) out[g * NCLASS + j] = l[j] - lse;
    }
}

// ---------------- launch ----------------
extern "C" void kernel_launch(void* const* d_in, const int* in_sizes, int n_in,
                              void* d_out, int out_size) {
    const float* x    = (const float*)d_in[0];
    const int*   ei   = (const int*)d_in[1];
    const float* W1   = (const float*)d_in[2];
    const float* b1   = (const float*)d_in[3];
    const float* W2   = (const float*)d_in[4];
    const float* b2   = (const float*)d_in[5];
    const float* W3   = (const float*)d_in[6];
    const float* b3   = (const float*)d_in[7];
    const float* att1 = (const float*)d_in[8];
    const float* att2 = (const float*)d_in[9];
    const float* lw1  = (const float*)d_in[10];
    const float* lb1  = (const float*)d_in[11];
    const float* lw2  = (const float*)d_in[12];
    const float* lb2  = (const float*)d_in[13];
    const float* lw3  = (const float*)d_in[14];
    const float* lb3  = (const float*)d_in[15];

    int E = in_sizes[1] / 2;

    cudaFuncSetAttribute(mega_kernel, cudaFuncAttributeMaxDynamicSharedMemorySize, SMEM_BYTES);
    mega_kernel<<<GRID, NTHREADS, SMEM_BYTES>>>(
        x, ei, E, W1, b1, W2, b2, W3, b3, att1, att2,
        lw1, lb1, lw2, lb2, lw3, lb3, (float*)d_out);
}